// round 2
// baseline (speedup 1.0000x reference)
#include <cuda_runtime.h>
#include <math.h>

#define B_  128
#define D_  512
#define H_  512
#define T_  500
#define NG_ 1536   // 3*H : [r|z|h]
#define NCTA 96

// ---------------- static device scratch (no runtime allocation) ----------------
__device__ float g_Wpack[D_ * NG_];              // [Wr|Wz|Wh] packed, 3 MB
__device__ float g_bpack[NG_];                   // [br|bz|bh]
__device__ float g_Acat[H_ * NG_];               // folded [Ar|Az|Ah], 3 MB
__device__ float g_ccat[NG_];                    // folded biases
__device__ float g_h[B_ * H_];                   // current hidden state
__device__ float g_rh[B_ * H_];                  // r * h
__device__ float g_G[B_ * 2 * H_];               // pre-activations [z|h]
__device__ float g_part[3 * B_ * H_];            // split-K partials for phase 2
__device__ float g_hist[(size_t)(T_ - 1) * B_ * H_];  // h history, ~131 MB

__device__ unsigned g_bar_arrive = 0;
__device__ unsigned g_bar_gen = 0;

__device__ __forceinline__ float sigmoidf_(float x) { return 1.f / (1.f + __expf(-x)); }

// ---------------- grid-wide barrier (all NCTA CTAs resident) ----------------
__device__ __forceinline__ void gbar() {
  __syncthreads();
  if (threadIdx.x == 0) {
    __threadfence();
    unsigned gen = *(volatile unsigned*)&g_bar_gen;
    if (atomicAdd(&g_bar_arrive, 1u) == NCTA - 1) {
      g_bar_arrive = 0;
      __threadfence();
      *(volatile unsigned*)&g_bar_gen = gen + 1;
    } else {
      while (*(volatile unsigned*)&g_bar_gen == gen) {}
    }
    __threadfence();
  }
  __syncthreads();
}

// ---------------- epilogue functors for the generic GEMM ----------------
struct EpiFold {
  const float *Ur, *Uz;
  __device__ __forceinline__ void operator()(int m, int n, float v) const {
    if (n < H_)            v += Ur[m * H_ + n];
    else if (n < 2 * H_)   v += Uz[m * H_ + (n - H_)];
    g_Acat[m * NG_ + n] = v;
  }
};

struct EpiStep1 {   // P = inputs@[Wz|Wh] + [bz|bh]
  __device__ __forceinline__ void operator()(int m, int n, float v) const {
    g_G[m * (2 * H_) + n] = v + g_bpack[H_ + n];
  }
};

struct EpiFinal {   // out[:, t+1, :] = hist_t @ Wo + bo
  float* out; const float* bo;
  __device__ __forceinline__ void operator()(int m, int n, float v) const {
    int t = m >> 7;
    int b = m & (B_ - 1);
    out[(size_t)b * ((size_t)T_ * D_) + (size_t)(t + 1) * D_ + n] = v + bo[n];
  }
};

// ---------------- generic tiled fp32 GEMM (setup / final projection) ----------------
template <int BN, class Epi>
__global__ void __launch_bounds__(4 * BN)
gemm_kernel(const float* __restrict__ A, const float* __restrict__ Bm,
            int K, int ldb, Epi epi) {
  constexpr int BM = 32, BK = 32;
  constexpr int NTHR = 4 * BN;
  __shared__ __align__(16) float As[BK][BM + 1];
  __shared__ __align__(16) float Bs[BK][BN];
  const int tid = threadIdx.x;
  const int bm = blockIdx.y * BM;
  const int bn = blockIdx.x * BN;
  const int tx = tid % (BN / 4);
  const int ty = tid / (BN / 4);
  float acc[2][4] = {};
  for (int k0 = 0; k0 < K; k0 += BK) {
    #pragma unroll
    for (int i = tid * 4; i < BM * BK; i += NTHR * 4) {
      int m = i / BK, k = i % BK;
      float4 v = *(const float4*)(A + (size_t)(bm + m) * K + k0 + k);
      As[k + 0][m] = v.x; As[k + 1][m] = v.y; As[k + 2][m] = v.z; As[k + 3][m] = v.w;
    }
    #pragma unroll
    for (int i = tid * 4; i < BK * BN; i += NTHR * 4) {
      int k = i / BN, n = i % BN;
      *(float4*)&Bs[k][n] = *(const float4*)(Bm + (size_t)(k0 + k) * ldb + bn + n);
    }
    __syncthreads();
    #pragma unroll
    for (int kk = 0; kk < BK; kk++) {
      float a0 = As[kk][ty * 2 + 0];
      float a1 = As[kk][ty * 2 + 1];
      float4 b4 = *(float4*)&Bs[kk][tx * 4];
      acc[0][0] = fmaf(a0, b4.x, acc[0][0]);
      acc[0][1] = fmaf(a0, b4.y, acc[0][1]);
      acc[0][2] = fmaf(a0, b4.z, acc[0][2]);
      acc[0][3] = fmaf(a0, b4.w, acc[0][3]);
      acc[1][0] = fmaf(a1, b4.x, acc[1][0]);
      acc[1][1] = fmaf(a1, b4.y, acc[1][1]);
      acc[1][2] = fmaf(a1, b4.z, acc[1][2]);
      acc[1][3] = fmaf(a1, b4.w, acc[1][3]);
    }
    __syncthreads();
  }
  #pragma unroll
  for (int i = 0; i < 2; i++)
    #pragma unroll
    for (int j = 0; j < 4; j++)
      epi(bm + ty * 2 + i, bn + tx * 4 + j, acc[i][j]);
}

// ---------------- persistent recurrence kernel ----------------
// 96 CTAs x 256 threads. Per step:
//   Stage A: G' = h @ Acat + ccat   (128x1536, K=512) -> r part to g_rh, z/h to g_G
//   Stage B: part = rh @ Uh          (128x512 split-K3) -> g_part
//   Stage C: gating + clip + history stash
__global__ void __launch_bounds__(256)
recur_kernel(const float* __restrict__ Uh) {
  const int tid = threadIdx.x;
  const int bid = blockIdx.x;
  const int tx = tid & 15;        // 16 col groups of 4
  const int ty = tid >> 4;        // 16 row groups of 2
  __shared__ __align__(16) float As[32][36];
  __shared__ __align__(16) float Bs[32][64];

  for (int t = 2; t < T_; t++) {
    // ---- Stage A ----
    {
      const int bm = (bid & 3) * 32;
      const int bn = (bid >> 2) * 64;
      float acc[2][4] = {};
      for (int k0 = 0; k0 < H_; k0 += 32) {
        {
          int m = tid >> 3, kq = tid & 7;
          float4 v = __ldcg((const float4*)&g_h[(bm + m) * H_ + k0 + kq * 4]);
          *(float4*)&As[m][kq * 4] = v;
        }
        #pragma unroll
        for (int it = 0; it < 2; it++) {
          int idx = tid + it * 256;
          int k = idx >> 4, nq = idx & 15;
          *(float4*)&Bs[k][nq * 4] =
              *(const float4*)&g_Acat[(size_t)(k0 + k) * NG_ + bn + nq * 4];
        }
        __syncthreads();
        #pragma unroll
        for (int k = 0; k < 32; k++) {
          float a0 = As[ty * 2 + 0][k];
          float a1 = As[ty * 2 + 1][k];
          float4 b = *(float4*)&Bs[k][tx * 4];
          acc[0][0] = fmaf(a0, b.x, acc[0][0]);
          acc[0][1] = fmaf(a0, b.y, acc[0][1]);
          acc[0][2] = fmaf(a0, b.z, acc[0][2]);
          acc[0][3] = fmaf(a0, b.w, acc[0][3]);
          acc[1][0] = fmaf(a1, b.x, acc[1][0]);
          acc[1][1] = fmaf(a1, b.y, acc[1][1]);
          acc[1][2] = fmaf(a1, b.z, acc[1][2]);
          acc[1][3] = fmaf(a1, b.w, acc[1][3]);
        }
        __syncthreads();
      }
      const int nbase = bn + tx * 4;
      #pragma unroll
      for (int i = 0; i < 2; i++) {
        int m = bm + ty * 2 + i;
        #pragma unroll
        for (int j = 0; j < 4; j++) {
          int n = nbase + j;
          float v = acc[i][j] + g_ccat[n];
          if (n < H_) {
            float h = __ldcg(&g_h[m * H_ + n]);
            g_rh[m * H_ + n] = sigmoidf_(v) * h;
          } else {
            g_G[m * (2 * H_) + (n - H_)] = v;
          }
        }
      }
    }
    gbar();

    // ---- Stage B: split-K3 over 32 tiles ----
    {
      const int tile = bid & 31;
      const int kc = bid >> 5;                        // 0,1,2
      const int bm = (tile & 3) * 32;
      const int bn = (tile >> 2) * 64;
      const int k0s = (kc == 0) ? 0 : (kc == 1 ? 192 : 352);
      const int k1  = (kc == 0) ? 192 : (kc == 1 ? 352 : 512);
      float acc[2][4] = {};
      for (int k0 = k0s; k0 < k1; k0 += 32) {
        {
          int m = tid >> 3, kq = tid & 7;
          float4 v = __ldcg((const float4*)&g_rh[(bm + m) * H_ + k0 + kq * 4]);
          *(float4*)&As[m][kq * 4] = v;
        }
        #pragma unroll
        for (int it = 0; it < 2; it++) {
          int idx = tid + it * 256;
          int k = idx >> 4, nq = idx & 15;
          *(float4*)&Bs[k][nq * 4] =
              *(const float4*)&Uh[(size_t)(k0 + k) * H_ + bn + nq * 4];
        }
        __syncthreads();
        #pragma unroll
        for (int k = 0; k < 32; k++) {
          float a0 = As[ty * 2 + 0][k];
          float a1 = As[ty * 2 + 1][k];
          float4 b = *(float4*)&Bs[k][tx * 4];
          acc[0][0] = fmaf(a0, b.x, acc[0][0]);
          acc[0][1] = fmaf(a0, b.y, acc[0][1]);
          acc[0][2] = fmaf(a0, b.z, acc[0][2]);
          acc[0][3] = fmaf(a0, b.w, acc[0][3]);
          acc[1][0] = fmaf(a1, b.x, acc[1][0]);
          acc[1][1] = fmaf(a1, b.y, acc[1][1]);
          acc[1][2] = fmaf(a1, b.z, acc[1][2]);
          acc[1][3] = fmaf(a1, b.w, acc[1][3]);
        }
        __syncthreads();
      }
      #pragma unroll
      for (int i = 0; i < 2; i++) {
        int m = bm + ty * 2 + i;
        float4 v = make_float4(acc[i][0], acc[i][1], acc[i][2], acc[i][3]);
        *(float4*)&g_part[kc * (B_ * H_) + m * H_ + bn + tx * 4] = v;
      }
    }
    gbar();

    // ---- Stage C: gating ----
    for (int idx = bid * 256 + tid; idx < B_ * H_; idx += NCTA * 256) {
      int m = idx >> 9, n = idx & (H_ - 1);
      float v = __ldcg(&g_part[idx]) + __ldcg(&g_part[B_ * H_ + idx]) +
                __ldcg(&g_part[2 * B_ * H_ + idx]);
      float z  = sigmoidf_(__ldcg(&g_G[m * (2 * H_) + n]));
      float hp = tanhf(__ldcg(&g_G[m * (2 * H_) + H_ + n]) + v);
      float h0 = __ldcg(&g_h[idx]);
      float hn = fminf(fmaxf(fmaf(z, hp - h0, h0), -5.f), 5.f);
      g_h[idx] = hn;
      g_hist[(size_t)(t - 1) * (B_ * H_) + idx] = hn;
    }
    gbar();
  }
}

// ---------------- small helper kernels ----------------
__global__ void pack_kernel(const float* __restrict__ Wr, const float* __restrict__ Wz,
                            const float* __restrict__ Wh, const float* __restrict__ br,
                            const float* __restrict__ bz, const float* __restrict__ bh) {
  int idx = blockIdx.x * blockDim.x + threadIdx.x;
  if (idx == 0) g_bar_arrive = 0;
  if (idx < NG_) {
    int sel = idx >> 9, jl = idx & 511;
    g_bpack[idx] = (sel == 0) ? br[jl] : (sel == 1) ? bz[jl] : bh[jl];
  }
  if (idx < D_ * NG_) {
    int d = idx / NG_, j = idx % NG_;
    int sel = j >> 9, jl = j & 511;
    const float* W = (sel == 0) ? Wr : (sel == 1) ? Wz : Wh;
    g_Wpack[idx] = W[d * H_ + jl];
  }
}

__global__ void ccat_kernel(const float* __restrict__ bo) {
  int w = (blockIdx.x * blockDim.x + threadIdx.x) >> 5;
  int lane = threadIdx.x & 31;
  if (w >= NG_) return;
  float acc = 0.f;
  for (int d = lane; d < D_; d += 32)
    acc = fmaf(bo[d], g_Wpack[(size_t)d * NG_ + w], acc);
  #pragma unroll
  for (int o = 16; o; o >>= 1) acc += __shfl_xor_sync(0xffffffffu, acc, o);
  if (lane == 0) g_ccat[w] = acc + g_bpack[w];
}

__global__ void copy0_kernel(const float* __restrict__ inputs, float* __restrict__ out) {
  int idx = blockIdx.x * blockDim.x + threadIdx.x;
  if (idx >= B_ * D_) return;
  int b = idx / D_, d = idx % D_;
  out[(size_t)b * ((size_t)T_ * D_) + d] = inputs[idx];
}

__global__ void combine1_kernel() {  // h1 = clip(sigmoid(Gz) * tanh(Gh))  (h0 = 0)
  int idx = blockIdx.x * blockDim.x + threadIdx.x;
  if (idx >= B_ * H_) return;
  int b = idx / H_, j = idx % H_;
  float z  = sigmoidf_(g_G[b * (2 * H_) + j]);
  float hp = tanhf(g_G[b * (2 * H_) + H_ + j]);
  float hn = fminf(fmaxf(z * hp, -5.f), 5.f);
  g_h[idx] = hn;
  g_hist[idx] = hn;
}

// ---------------- launch ----------------
extern "C" void kernel_launch(void* const* d_in, const int* in_sizes, int n_in,
                              void* d_out, int out_size) {
  const float* inputs = (const float*)d_in[0];
  const float* Wz = (const float*)d_in[1];
  const float* Wr = (const float*)d_in[2];
  const float* Wh = (const float*)d_in[3];
  const float* Uz = (const float*)d_in[4];
  const float* Ur = (const float*)d_in[5];
  const float* Uh = (const float*)d_in[6];
  const float* bz = (const float*)d_in[7];
  const float* br = (const float*)d_in[8];
  const float* bh = (const float*)d_in[9];
  const float* Wo = (const float*)d_in[10];
  const float* bo = (const float*)d_in[11];
  float* out = (float*)d_out;

  float *pWpack, *pHist;
  cudaGetSymbolAddress((void**)&pWpack, g_Wpack);
  cudaGetSymbolAddress((void**)&pHist, g_hist);

  // one-time (per launch) weight folding
  pack_kernel<<<(D_ * NG_ + 255) / 256, 256>>>(Wr, Wz, Wh, br, bz, bh);
  ccat_kernel<<<(NG_ * 32 + 255) / 256, 256>>>(bo);
  gemm_kernel<64, EpiFold><<<dim3(NG_ / 64, H_ / 32), 256>>>(
      Wo, pWpack, D_, NG_, EpiFold{Ur, Uz});

  // t = 0 output is the raw input
  copy0_kernel<<<(B_ * D_ + 255) / 256, 256>>>(inputs, out);

  // step 1 (h0 = 0): only x@Wz, x@Wh matter
  gemm_kernel<64, EpiStep1><<<dim3(1024 / 64, B_ / 32), 256>>>(
      inputs, pWpack + H_, D_, NG_, EpiStep1{});
  combine1_kernel<<<(B_ * H_ + 255) / 256, 256>>>();

  // steps 2..T-1 : ONE persistent kernel (grid-wide barriers inside)
  recur_kernel<<<NCTA, 256>>>(Uh);

  // deferred output projection: out[:, 1.., :] = hist @ Wo + bo
  gemm_kernel<64, EpiFinal><<<dim3(H_ / 64, (T_ - 1) * B_ / 32), 256>>>(
      pHist, Wo, H_, H_, EpiFinal{out, bo});
}

// round 3
// speedup vs baseline: 1.0908x; 1.0908x over previous
#include <cuda_runtime.h>
#include <math.h>

#define B_  128
#define D_  512
#define H_  512
#define T_  500
#define NG_ 1536   // 3*H : [r|z|h]
#define NCTA 128

// ---------------- static device scratch ----------------
__device__ float g_Wpack[D_ * NG_];              // [Wr|Wz|Wh] packed
__device__ float g_bpack[NG_];                   // [br|bz|bh]
__device__ float g_Acat[H_ * NG_];               // folded [Ar|Az|Ah]
__device__ float g_ccat[NG_];                    // folded biases
__device__ float g_h[B_ * H_];                   // hidden state
__device__ float g_rh[B_ * H_];                  // r * h
__device__ float g_G[B_ * 1024];                 // pre-activations [z | h]
__device__ float g_hist[(size_t)(T_ - 1) * B_ * H_];  // h history

__device__ unsigned g_bar_arrive = 0;
__device__ unsigned g_bar_gen = 0;

__device__ __forceinline__ float sigmoidf_(float x) { return 1.f / (1.f + __expf(-x)); }

__device__ __forceinline__ void gbar() {
  __syncthreads();
  if (threadIdx.x == 0) {
    __threadfence();
    unsigned gen = *(volatile unsigned*)&g_bar_gen;
    if (atomicAdd(&g_bar_arrive, 1u) == NCTA - 1) {
      g_bar_arrive = 0;
      __threadfence();
      *(volatile unsigned*)&g_bar_gen = gen + 1;
    } else {
      while (*(volatile unsigned*)&g_bar_gen == gen) {}
    }
    __threadfence();
  }
  __syncthreads();
}

// ---------------- epilogues for setup / final GEMMs ----------------
struct EpiFold {
  const float *Ur, *Uz;
  __device__ __forceinline__ void operator()(int m, int n, float v) const {
    if (n < H_)            v += Ur[m * H_ + n];
    else if (n < 2 * H_)   v += Uz[m * H_ + (n - H_)];
    g_Acat[m * NG_ + n] = v;
  }
};
struct EpiStep1 {   // G = inputs@[Wz|Wh] + [bz|bh]
  __device__ __forceinline__ void operator()(int m, int n, float v) const {
    g_G[m * 1024 + n] = v + g_bpack[H_ + n];
  }
};
struct EpiFinal {   // out[:, t+1, :] = hist_t @ Wo + bo
  float* out; const float* bo;
  __device__ __forceinline__ void operator()(int m, int n, float v) const {
    int t = m >> 7;
    int b = m & (B_ - 1);
    out[(size_t)b * ((size_t)T_ * D_) + (size_t)(t + 1) * D_ + n] = v + bo[n];
  }
};

// ---------------- generic tiled fp32 GEMM (setup / final projection) ----------------
template <int BN, class Epi>
__global__ void __launch_bounds__(4 * BN)
gemm_kernel(const float* __restrict__ A, const float* __restrict__ Bm,
            int K, int ldb, Epi epi) {
  constexpr int BM = 32, BK = 32;
  constexpr int NTHR = 4 * BN;
  __shared__ __align__(16) float As[BK][BM + 1];
  __shared__ __align__(16) float Bs[BK][BN];
  const int tid = threadIdx.x;
  const int bm = blockIdx.y * BM;
  const int bn = blockIdx.x * BN;
  const int tx = tid % (BN / 4);
  const int ty = tid / (BN / 4);
  float acc[2][4] = {};
  for (int k0 = 0; k0 < K; k0 += BK) {
    #pragma unroll
    for (int i = tid * 4; i < BM * BK; i += NTHR * 4) {
      int m = i / BK, k = i % BK;
      float4 v = *(const float4*)(A + (size_t)(bm + m) * K + k0 + k);
      As[k + 0][m] = v.x; As[k + 1][m] = v.y; As[k + 2][m] = v.z; As[k + 3][m] = v.w;
    }
    #pragma unroll
    for (int i = tid * 4; i < BK * BN; i += NTHR * 4) {
      int k = i / BN, n = i % BN;
      *(float4*)&Bs[k][n] = *(const float4*)(Bm + (size_t)(k0 + k) * ldb + bn + n);
    }
    __syncthreads();
    #pragma unroll
    for (int kk = 0; kk < BK; kk++) {
      float a0 = As[kk][ty * 2 + 0];
      float a1 = As[kk][ty * 2 + 1];
      float4 b4 = *(float4*)&Bs[kk][tx * 4];
      acc[0][0] = fmaf(a0, b4.x, acc[0][0]);
      acc[0][1] = fmaf(a0, b4.y, acc[0][1]);
      acc[0][2] = fmaf(a0, b4.z, acc[0][2]);
      acc[0][3] = fmaf(a0, b4.w, acc[0][3]);
      acc[1][0] = fmaf(a1, b4.x, acc[1][0]);
      acc[1][1] = fmaf(a1, b4.y, acc[1][1]);
      acc[1][2] = fmaf(a1, b4.z, acc[1][2]);
      acc[1][3] = fmaf(a1, b4.w, acc[1][3]);
    }
    __syncthreads();
  }
  #pragma unroll
  for (int i = 0; i < 2; i++)
    #pragma unroll
    for (int j = 0; j < 4; j++)
      epi(bm + ty * 2 + i, bn + tx * 4 + j, acc[i][j]);
}

// ---------------- persistent recurrence kernel ----------------
// 128 CTAs x 128 threads (1 CTA/SM, 1 warp/SMSP). Per step:
//   Stage A: [rh | Gz | Gh] = epilogue(h @ Acat + ccat)   tiles 32x48, K=512
//   Stage B: h' = gate(rh @ Uh)                            tiles 16x32, K=512 (full)
// 2 grid barriers per step.
__global__ void __launch_bounds__(128)
recur_kernel(const float* __restrict__ Uh) {
  const int tid = threadIdx.x;
  const int bid = blockIdx.x;
  __shared__ __align__(16) float As[32][36];   // h tile (m x k)
  __shared__ __align__(16) float Bs[32][48];   // Acat tile (k x n)
  __shared__ __align__(16) float As2[16][36];  // rh tile
  __shared__ __align__(16) float Bs2[32][36];  // Uh tile

  // stage A coords: tile 32x48, microtile 2x6
  const int txA = tid & 7;          // 8 col groups of 6
  const int tyA = tid >> 3;         // 16 row groups of 2
  const int bmA = (bid & 3) * 32;
  const int bnA = (bid >> 2) * 48;
  // stage B coords: tile 16x32, microtile 1x4
  const int txB = tid & 7;
  const int tyB = tid >> 3;
  const int bmB = (bid & 7) * 16;
  const int bnB = (bid >> 3) * 32;

  for (int t = 2; t < T_; t++) {
    // ================= Stage A =================
    {
      float acc[2][6] = {};
      // prefetch k0 = 0
      float4 pa0, pa1, pb0, pb1, pb2;
      {
        int l0 = tid, l1 = tid + 128;
        pa0 = __ldcg((const float4*)&g_h[(bmA + (l0 >> 3)) * H_ + (l0 & 7) * 4]);
        pa1 = __ldcg((const float4*)&g_h[(bmA + (l1 >> 3)) * H_ + (l1 & 7) * 4]);
        int r0 = tid / 12, c0 = tid % 12;
        int r1 = (tid + 128) / 12, c1 = (tid + 128) % 12;
        int r2 = (tid + 256) / 12, c2 = (tid + 256) % 12;
        pb0 = __ldg((const float4*)&g_Acat[(size_t)r0 * NG_ + bnA + c0 * 4]);
        pb1 = __ldg((const float4*)&g_Acat[(size_t)r1 * NG_ + bnA + c1 * 4]);
        pb2 = __ldg((const float4*)&g_Acat[(size_t)r2 * NG_ + bnA + c2 * 4]);
      }
      for (int k0 = 0; k0 < H_; k0 += 32) {
        // store prefetched slab
        {
          int l0 = tid, l1 = tid + 128;
          *(float4*)&As[l0 >> 3][(l0 & 7) * 4] = pa0;
          *(float4*)&As[l1 >> 3][(l1 & 7) * 4] = pa1;
          int r0 = tid / 12, c0 = tid % 12;
          int r1 = (tid + 128) / 12, c1 = (tid + 128) % 12;
          int r2 = (tid + 256) / 12, c2 = (tid + 256) % 12;
          *(float4*)&Bs[r0][c0 * 4] = pb0;
          *(float4*)&Bs[r1][c1 * 4] = pb1;
          *(float4*)&Bs[r2][c2 * 4] = pb2;
        }
        __syncthreads();
        // prefetch next slab
        if (k0 + 32 < H_) {
          int kn = k0 + 32;
          int l0 = tid, l1 = tid + 128;
          pa0 = __ldcg((const float4*)&g_h[(bmA + (l0 >> 3)) * H_ + kn + (l0 & 7) * 4]);
          pa1 = __ldcg((const float4*)&g_h[(bmA + (l1 >> 3)) * H_ + kn + (l1 & 7) * 4]);
          int r0 = tid / 12, c0 = tid % 12;
          int r1 = (tid + 128) / 12, c1 = (tid + 128) % 12;
          int r2 = (tid + 256) / 12, c2 = (tid + 256) % 12;
          pb0 = __ldg((const float4*)&g_Acat[(size_t)(kn + r0) * NG_ + bnA + c0 * 4]);
          pb1 = __ldg((const float4*)&g_Acat[(size_t)(kn + r1) * NG_ + bnA + c1 * 4]);
          pb2 = __ldg((const float4*)&g_Acat[(size_t)(kn + r2) * NG_ + bnA + c2 * 4]);
        }
        // compute
        #pragma unroll
        for (int k = 0; k < 32; k += 4) {
          float4 a0 = *(float4*)&As[tyA * 2 + 0][k];
          float4 a1 = *(float4*)&As[tyA * 2 + 1][k];
          #pragma unroll
          for (int kk = 0; kk < 4; kk++) {
            float va0 = (kk == 0) ? a0.x : (kk == 1) ? a0.y : (kk == 2) ? a0.z : a0.w;
            float va1 = (kk == 0) ? a1.x : (kk == 1) ? a1.y : (kk == 2) ? a1.z : a1.w;
            float2 b0 = *(float2*)&Bs[k + kk][txA * 6 + 0];
            float2 b1 = *(float2*)&Bs[k + kk][txA * 6 + 2];
            float2 b2 = *(float2*)&Bs[k + kk][txA * 6 + 4];
            acc[0][0] = fmaf(va0, b0.x, acc[0][0]);
            acc[0][1] = fmaf(va0, b0.y, acc[0][1]);
            acc[0][2] = fmaf(va0, b1.x, acc[0][2]);
            acc[0][3] = fmaf(va0, b1.y, acc[0][3]);
            acc[0][4] = fmaf(va0, b2.x, acc[0][4]);
            acc[0][5] = fmaf(va0, b2.y, acc[0][5]);
            acc[1][0] = fmaf(va1, b0.x, acc[1][0]);
            acc[1][1] = fmaf(va1, b0.y, acc[1][1]);
            acc[1][2] = fmaf(va1, b1.x, acc[1][2]);
            acc[1][3] = fmaf(va1, b1.y, acc[1][3]);
            acc[1][4] = fmaf(va1, b2.x, acc[1][4]);
            acc[1][5] = fmaf(va1, b2.y, acc[1][5]);
          }
        }
        __syncthreads();
      }
      // epilogue
      #pragma unroll
      for (int i = 0; i < 2; i++) {
        int m = bmA + tyA * 2 + i;
        #pragma unroll
        for (int j = 0; j < 6; j++) {
          int n = bnA + txA * 6 + j;
          float v = acc[i][j] + __ldg(&g_ccat[n]);
          if (n < H_) {
            float h = __ldcg(&g_h[m * H_ + n]);
            g_rh[m * H_ + n] = sigmoidf_(v) * h;
          } else {
            g_G[m * 1024 + (n - H_)] = v;
          }
        }
      }
    }
    gbar();

    // ================= Stage B (full K, gating epilogue) =================
    {
      float acc[4] = {};
      float4 pa, pb0, pb1;
      {
        pa  = __ldcg((const float4*)&g_rh[(bmB + (tid >> 3)) * H_ + (tid & 7) * 4]);
        int l0 = tid, l1 = tid + 128;
        pb0 = __ldg((const float4*)&Uh[(size_t)(l0 >> 3) * H_ + bnB + (l0 & 7) * 4]);
        pb1 = __ldg((const float4*)&Uh[(size_t)(l1 >> 3) * H_ + bnB + (l1 & 7) * 4]);
      }
      for (int k0 = 0; k0 < H_; k0 += 32) {
        *(float4*)&As2[tid >> 3][(tid & 7) * 4] = pa;
        {
          int l0 = tid, l1 = tid + 128;
          *(float4*)&Bs2[l0 >> 3][(l0 & 7) * 4] = pb0;
          *(float4*)&Bs2[l1 >> 3][(l1 & 7) * 4] = pb1;
        }
        __syncthreads();
        if (k0 + 32 < H_) {
          int kn = k0 + 32;
          pa  = __ldcg((const float4*)&g_rh[(bmB + (tid >> 3)) * H_ + kn + (tid & 7) * 4]);
          int l0 = tid, l1 = tid + 128;
          pb0 = __ldg((const float4*)&Uh[(size_t)(kn + (l0 >> 3)) * H_ + bnB + (l0 & 7) * 4]);
          pb1 = __ldg((const float4*)&Uh[(size_t)(kn + (l1 >> 3)) * H_ + bnB + (l1 & 7) * 4]);
        }
        #pragma unroll
        for (int k = 0; k < 32; k += 4) {
          float4 a = *(float4*)&As2[tyB][k];
          #pragma unroll
          for (int kk = 0; kk < 4; kk++) {
            float va = (kk == 0) ? a.x : (kk == 1) ? a.y : (kk == 2) ? a.z : a.w;
            float4 b = *(float4*)&Bs2[k + kk][txB * 4];
            acc[0] = fmaf(va, b.x, acc[0]);
            acc[1] = fmaf(va, b.y, acc[1]);
            acc[2] = fmaf(va, b.z, acc[2]);
            acc[3] = fmaf(va, b.w, acc[3]);
          }
        }
        __syncthreads();
      }
      // gating epilogue (owns each output uniquely)
      int m = bmB + tyB;
      #pragma unroll
      for (int j = 0; j < 4; j++) {
        int n = bnB + txB * 4 + j;
        float z  = sigmoidf_(__ldcg(&g_G[m * 1024 + n]));
        float hp = tanhf(__ldcg(&g_G[m * 1024 + H_ + n]) + acc[j]);
        float h0 = __ldcg(&g_h[m * H_ + n]);
        float hn = fminf(fmaxf(fmaf(z, hp - h0, h0), -5.f), 5.f);
        g_h[m * H_ + n] = hn;
        g_hist[(size_t)(t - 1) * (B_ * H_) + m * H_ + n] = hn;
      }
    }
    gbar();
  }
}

// ---------------- small helper kernels ----------------
__global__ void pack_kernel(const float* __restrict__ Wr, const float* __restrict__ Wz,
                            const float* __restrict__ Wh, const float* __restrict__ br,
                            const float* __restrict__ bz, const float* __restrict__ bh) {
  int idx = blockIdx.x * blockDim.x + threadIdx.x;
  if (idx == 0) g_bar_arrive = 0;
  if (idx < NG_) {
    int sel = idx >> 9, jl = idx & 511;
    g_bpack[idx] = (sel == 0) ? br[jl] : (sel == 1) ? bz[jl] : bh[jl];
  }
  if (idx < D_ * NG_) {
    int d = idx / NG_, j = idx % NG_;
    int sel = j >> 9, jl = j & 511;
    const float* W = (sel == 0) ? Wr : (sel == 1) ? Wz : Wh;
    g_Wpack[idx] = W[d * H_ + jl];
  }
}

__global__ void ccat_kernel(const float* __restrict__ bo) {
  int w = (blockIdx.x * blockDim.x + threadIdx.x) >> 5;
  int lane = threadIdx.x & 31;
  if (w >= NG_) return;
  float acc = 0.f;
  for (int d = lane; d < D_; d += 32)
    acc = fmaf(bo[d], g_Wpack[(size_t)d * NG_ + w], acc);
  #pragma unroll
  for (int o = 16; o; o >>= 1) acc += __shfl_xor_sync(0xffffffffu, acc, o);
  if (lane == 0) g_ccat[w] = acc + g_bpack[w];
}

__global__ void copy0_kernel(const float* __restrict__ inputs, float* __restrict__ out) {
  int idx = blockIdx.x * blockDim.x + threadIdx.x;
  if (idx >= B_ * D_) return;
  int b = idx / D_, d = idx % D_;
  out[(size_t)b * ((size_t)T_ * D_) + d] = inputs[idx];
}

__global__ void combine1_kernel() {  // h1 = clip(sigmoid(Gz) * tanh(Gh))  (h0 = 0)
  int idx = blockIdx.x * blockDim.x + threadIdx.x;
  if (idx >= B_ * H_) return;
  int b = idx / H_, j = idx % H_;
  float z  = sigmoidf_(g_G[b * 1024 + j]);
  float hp = tanhf(g_G[b * 1024 + H_ + j]);
  float hn = fminf(fmaxf(z * hp, -5.f), 5.f);
  g_h[idx] = hn;
  g_hist[idx] = hn;
}

// ---------------- launch ----------------
extern "C" void kernel_launch(void* const* d_in, const int* in_sizes, int n_in,
                              void* d_out, int out_size) {
  const float* inputs = (const float*)d_in[0];
  const float* Wz = (const float*)d_in[1];
  const float* Wr = (const float*)d_in[2];
  const float* Wh = (const float*)d_in[3];
  const float* Uz = (const float*)d_in[4];
  const float* Ur = (const float*)d_in[5];
  const float* Uh = (const float*)d_in[6];
  const float* bz = (const float*)d_in[7];
  const float* br = (const float*)d_in[8];
  const float* bh = (const float*)d_in[9];
  const float* Wo = (const float*)d_in[10];
  const float* bo = (const float*)d_in[11];
  float* out = (float*)d_out;

  float *pWpack, *pHist;
  cudaGetSymbolAddress((void**)&pWpack, g_Wpack);
  cudaGetSymbolAddress((void**)&pHist, g_hist);

  // setup: pack + fold weights
  pack_kernel<<<(D_ * NG_ + 255) / 256, 256>>>(Wr, Wz, Wh, br, bz, bh);
  ccat_kernel<<<(NG_ * 32 + 255) / 256, 256>>>(bo);
  gemm_kernel<64, EpiFold><<<dim3(NG_ / 64, H_ / 32), 256>>>(
      Wo, pWpack, D_, NG_, EpiFold{Ur, Uz});

  // step 1 (h0 = 0): only x@Wz, x@Wh matter
  gemm_kernel<64, EpiStep1><<<dim3(1024 / 64, B_ / 32), 256>>>(
      inputs, pWpack + H_, D_, NG_, EpiStep1{});
  combine1_kernel<<<(B_ * H_ + 255) / 256, 256>>>();

  // steps 2..T-1 : ONE persistent kernel
  recur_kernel<<<NCTA, 128>>>(Uh);

  // t = 0 output is the raw input (independent; placed late)
  copy0_kernel<<<(B_ * D_ + 255) / 256, 256>>>(inputs, out);

  // deferred output projection: out[:, 1.., :] = hist @ Wo + bo
  gemm_kernel<64, EpiFinal><<<dim3(H_ / 64, (T_ - 1) * B_ / 32), 256>>>(
      pHist, Wo, H_, H_, EpiFinal{out, bo});
}

// round 6
// speedup vs baseline: 2.7005x; 2.4757x over previous
#include <cuda_runtime.h>
#include <cuda_bf16.h>
#include <math.h>
#include <stdint.h>

#define B_  128
#define D_  512
#define H_  512
#define T_  500
#define NG_ 1536   // 3*H : [r|z|h]
#define NCTA 96

// ---------------- static device scratch ----------------
__device__ float g_Wpack[D_ * NG_];
__device__ float g_bpack[NG_];
__device__ float g_Acat[H_ * NG_];               // [k=512][g=1536] fp32
__device__ float g_ccat[NG_];
__device__ float g_h[B_ * H_];
__device__ float g_Gz[B_ * H_];
__device__ float g_Gh[B_ * H_];
__device__ __nv_bfloat16 g_Ath[NG_ * H_];        // Acat^T hi  [g][k]
__device__ __nv_bfloat16 g_Atl[NG_ * H_];
__device__ __nv_bfloat16 g_Uth[H_ * H_];         // Uh^T hi    [n][k]
__device__ __nv_bfloat16 g_Utl[H_ * H_];
__device__ __nv_bfloat16 g_Woth[H_ * D_];        // Wo^T hi    [n][k]
__device__ __nv_bfloat16 g_Wotl[H_ * D_];
__device__ __nv_bfloat16 g_hh[B_ * H_];          // h split
__device__ __nv_bfloat16 g_hl[B_ * H_];
__device__ __nv_bfloat16 g_rhh[B_ * H_];         // (r*h) split
__device__ __nv_bfloat16 g_rhl[B_ * H_];
__device__ __nv_bfloat16 g_histh[(size_t)(T_ - 1) * B_ * H_];
__device__ __nv_bfloat16 g_histl[(size_t)(T_ - 1) * B_ * H_];

__device__ unsigned g_bar_arrive = 0;
__device__ unsigned g_bar_gen = 0;

__device__ __forceinline__ float sigmoidf_(float x) { return 1.f / (1.f + __expf(-x)); }

__device__ __forceinline__ void gbar() {
  __syncthreads();
  if (threadIdx.x == 0) {
    __threadfence();
    unsigned gen = *(volatile unsigned*)&g_bar_gen;
    if (atomicAdd(&g_bar_arrive, 1u) == NCTA - 1) {
      g_bar_arrive = 0;
      __threadfence();
      *(volatile unsigned*)&g_bar_gen = gen + 1;
    } else {
      while (*(volatile unsigned*)&g_bar_gen == gen) {}
    }
    __threadfence();
  }
  __syncthreads();
}

// ---------------- mma.sync / ldmatrix / cp.async primitives (sm_80 PTX) ----------------
__device__ __forceinline__ uint32_t smem_u32(const void* p) {
  uint32_t a;
  asm("{ .reg .u64 t; cvta.to.shared.u64 t, %1; cvt.u32.u64 %0, t; }" : "=r"(a) : "l"(p));
  return a;
}
__device__ __forceinline__ void cp16(uint32_t dst, const void* src) {
  asm volatile("cp.async.cg.shared.global [%0], [%1], 16;" :: "r"(dst), "l"(src));
}
#define CP_COMMIT() asm volatile("cp.async.commit_group;" ::: "memory")
#define CP_WAIT(n)  asm volatile("cp.async.wait_group %0;" :: "n"(n) : "memory")
__device__ __forceinline__ void lsm4(uint32_t* r, uint32_t a) {
  asm volatile("ldmatrix.sync.aligned.m8n8.x4.shared.b16 {%0,%1,%2,%3}, [%4];"
               : "=r"(r[0]), "=r"(r[1]), "=r"(r[2]), "=r"(r[3]) : "r"(a));
}
__device__ __forceinline__ void lsm2(uint32_t* r, uint32_t a) {
  asm volatile("ldmatrix.sync.aligned.m8n8.x2.shared.b16 {%0,%1}, [%2];"
               : "=r"(r[0]), "=r"(r[1]) : "r"(a));
}
__device__ __forceinline__ void mma_bf16(float* d, const uint32_t* a, const uint32_t* b) {
  asm volatile(
      "mma.sync.aligned.m16n8k16.row.col.f32.bf16.bf16.f32 "
      "{%0,%1,%2,%3}, {%4,%5,%6,%7}, {%8,%9}, {%0,%1,%2,%3};"
      : "+f"(d[0]), "+f"(d[1]), "+f"(d[2]), "+f"(d[3])
      : "r"(a[0]), "r"(a[1]), "r"(a[2]), "r"(a[3]), "r"(b[0]), "r"(b[1]));
}
// swizzled smem tile: row r (128B) at r*128, 16B chunk c at ((c ^ (r&7))<<4)
__device__ __forceinline__ uint32_t swz(int r, int c) {
  return (uint32_t)(r * 128 + ((c ^ (r & 7)) << 4));
}

// ---------------- persistent recurrence kernel: 96 CTAs x 256 thr ----------------
// Stage A: C[128,1536] = h @ Acat (+3-way epilogue), tiles [32m x 64n], 4m x 24n groups
// Stage B: C[128,512]  = rh @ Uh (gating epilogue), tiles [32m x 32n], 64 CTAs
// smem: buf k (k&1): base = 24576*k: A_hi@0(4KB) A_lo@4096 B_hi@8192(8KB) B_lo@16384
__global__ void __launch_bounds__(256)
recur_kernel() {
  __shared__ __align__(128) char smem[49152];
  const uint32_t sb = smem_u32(smem);
  const int tid = threadIdx.x, bid = blockIdx.x;
  const int w = tid >> 5, lid = tid & 31;
  const int g = lid >> 2, tig = lid & 3;
  // stage A ids
  const int m0A = (bid & 3) * 32;
  const int cgA = bid >> 2;
  const int n0A = cgA * 64;
  const int wm = (w & 1) * 16;           // warp m offset within 32-row tile
  const int wnA = (w >> 1) * 16;         // warp n offset within 64-col tile
  // stage B ids (bid < 64)
  const int m0B = (bid & 3) * 32;
  const int n0B = (bid >> 2) * 32;
  const int wnB = (w >> 1) * 8;
  // ldmatrix lane rows
  const int laneRA = wm + (lid & 15);                       // A tile row
  const int laneRBA = wnA + (lid & 7) + ((lid >> 4) << 3);  // B tile row (stage A, x4)
  const int laneRBB = wnB + (lid & 7);                      // B tile row (stage B, x2)
  // load indexers
  const int lr = tid >> 3, lc = tid & 7;

  for (int t = 2; t < T_; t++) {
    // ================= Stage A =================
    {
      float acc0[4] = {}, acc1[4] = {};
      // pipelined loads over 8 k64-chunks
      #pragma unroll 1
      for (int kc = 0; kc < 8; kc++) {
        if (kc == 0) {
          uint32_t base = sb;
          int eoff = (m0A + lr) * 512 + lc * 8;
          cp16(base + swz(lr, lc), &g_hh[eoff]);
          cp16(base + 4096 + swz(lr, lc), &g_hl[eoff]);
          #pragma unroll
          for (int i = 0; i < 2; i++) {
            int idx = tid + i * 256, rb = idx >> 3, cb = idx & 7;
            int eo = (n0A + rb) * 512 + cb * 8;
            cp16(base + 8192 + swz(rb, cb), &g_Ath[eo]);
            cp16(base + 16384 + swz(rb, cb), &g_Atl[eo]);
          }
          CP_COMMIT();
        }
        if (kc < 7) {
          uint32_t base = sb + ((kc + 1) & 1) * 24576;
          int ko = (kc + 1) * 64;
          int eoff = (m0A + lr) * 512 + ko + lc * 8;
          cp16(base + swz(lr, lc), &g_hh[eoff]);
          cp16(base + 4096 + swz(lr, lc), &g_hl[eoff]);
          #pragma unroll
          for (int i = 0; i < 2; i++) {
            int idx = tid + i * 256, rb = idx >> 3, cb = idx & 7;
            int eo = (n0A + rb) * 512 + ko + cb * 8;
            cp16(base + 8192 + swz(rb, cb), &g_Ath[eo]);
            cp16(base + 16384 + swz(rb, cb), &g_Atl[eo]);
          }
          CP_COMMIT();
          CP_WAIT(1);
        } else {
          CP_WAIT(0);
        }
        __syncthreads();
        uint32_t base = sb + (kc & 1) * 24576;
        #pragma unroll
        for (int s = 0; s < 4; s++) {
          int cA = 2 * s + (lid >> 4);
          int cB = 2 * s + ((lid >> 3) & 1);
          uint32_t aAddr = base + swz(laneRA, cA);
          uint32_t bAddr = base + 8192 + swz(laneRBA, cB);
          uint32_t Ah[4], Al[4], Bh[4], Bl[4];
          lsm4(Ah, aAddr);
          lsm4(Al, aAddr + 4096);
          lsm4(Bh, bAddr);
          lsm4(Bl, bAddr + 8192);
          mma_bf16(acc0, Ah, Bh);
          mma_bf16(acc0, Ah, Bl);
          mma_bf16(acc0, Al, Bh);
          mma_bf16(acc1, Ah, Bh + 2);
          mma_bf16(acc1, Ah, Bl + 2);
          mma_bf16(acc1, Al, Bh + 2);
        }
        __syncthreads();
      }
      // epilogue
      const int m1 = m0A + wm + g, m2 = m1 + 8;
      #pragma unroll
      for (int nt = 0; nt < 2; nt++) {
        float* a = nt ? acc1 : acc0;
        int n = n0A + wnA + nt * 8 + tig * 2;
        float2 cc = *(const float2*)&g_ccat[n];
        float v00 = a[0] + cc.x, v01 = a[1] + cc.y;
        float v10 = a[2] + cc.x, v11 = a[3] + cc.y;
        int u = n & 511;
        if (cgA < 8) {          // r gates -> rh split
          float2 hA = __ldcg((const float2*)&g_h[m1 * 512 + u]);
          float2 hB = __ldcg((const float2*)&g_h[m2 * 512 + u]);
          float rh00 = sigmoidf_(v00) * hA.x, rh01 = sigmoidf_(v01) * hA.y;
          float rh10 = sigmoidf_(v10) * hB.x, rh11 = sigmoidf_(v11) * hB.y;
          __nv_bfloat162 ph, pl;
          ph.x = __float2bfloat16(rh00); ph.y = __float2bfloat16(rh01);
          pl.x = __float2bfloat16(rh00 - __bfloat162float(ph.x));
          pl.y = __float2bfloat16(rh01 - __bfloat162float(ph.y));
          *(__nv_bfloat162*)&g_rhh[m1 * 512 + u] = ph;
          *(__nv_bfloat162*)&g_rhl[m1 * 512 + u] = pl;
          ph.x = __float2bfloat16(rh10); ph.y = __float2bfloat16(rh11);
          pl.x = __float2bfloat16(rh10 - __bfloat162float(ph.x));
          pl.y = __float2bfloat16(rh11 - __bfloat162float(ph.y));
          *(__nv_bfloat162*)&g_rhh[m2 * 512 + u] = ph;
          *(__nv_bfloat162*)&g_rhl[m2 * 512 + u] = pl;
        } else if (cgA < 16) {  // z preacts
          *(float2*)&g_Gz[m1 * 512 + u] = make_float2(v00, v01);
          *(float2*)&g_Gz[m2 * 512 + u] = make_float2(v10, v11);
        } else {                // h preacts
          *(float2*)&g_Gh[m1 * 512 + u] = make_float2(v00, v01);
          *(float2*)&g_Gh[m2 * 512 + u] = make_float2(v10, v11);
        }
      }
    }
    gbar();

    // ================= Stage B (64 CTAs) =================
    if (bid < 64) {
      float acc[4] = {};
      #pragma unroll 1
      for (int kc = 0; kc < 8; kc++) {
        if (kc == 0) {
          uint32_t base = sb;
          int eoff = (m0B + lr) * 512 + lc * 8;
          cp16(base + swz(lr, lc), &g_rhh[eoff]);
          cp16(base + 4096 + swz(lr, lc), &g_rhl[eoff]);
          int eo = (n0B + lr) * 512 + lc * 8;
          cp16(base + 8192 + swz(lr, lc), &g_Uth[eo]);
          cp16(base + 16384 + swz(lr, lc), &g_Utl[eo]);
          CP_COMMIT();
        }
        if (kc < 7) {
          uint32_t base = sb + ((kc + 1) & 1) * 24576;
          int ko = (kc + 1) * 64;
          int eoff = (m0B + lr) * 512 + ko + lc * 8;
          cp16(base + swz(lr, lc), &g_rhh[eoff]);
          cp16(base + 4096 + swz(lr, lc), &g_rhl[eoff]);
          int eo = (n0B + lr) * 512 + ko + lc * 8;
          cp16(base + 8192 + swz(lr, lc), &g_Uth[eo]);
          cp16(base + 16384 + swz(lr, lc), &g_Utl[eo]);
          CP_COMMIT();
          CP_WAIT(1);
        } else {
          CP_WAIT(0);
        }
        __syncthreads();
        uint32_t base = sb + (kc & 1) * 24576;
        #pragma unroll
        for (int s = 0; s < 4; s++) {
          int cA = 2 * s + (lid >> 4);
          int cB = 2 * s + ((lid >> 3) & 1);
          uint32_t aAddr = base + swz(laneRA, cA);
          uint32_t bAddr = base + 8192 + swz(laneRBB, cB);
          uint32_t Ah[4], Al[4], Bh[2], Bl[2];
          lsm4(Ah, aAddr);
          lsm4(Al, aAddr + 4096);
          lsm2(Bh, bAddr);
          lsm2(Bl, bAddr + 8192);
          mma_bf16(acc, Ah, Bh);
          mma_bf16(acc, Ah, Bl);
          mma_bf16(acc, Al, Bh);
        }
        __syncthreads();
      }
      // gating epilogue
      const int n = n0B + wnB + tig * 2;
      const int m1 = m0B + wm + g;
      #pragma unroll
      for (int rr = 0; rr < 2; rr++) {
        int m = m1 + rr * 8;
        float q0 = acc[rr * 2 + 0], q1 = acc[rr * 2 + 1];
        float2 gz = __ldcg((const float2*)&g_Gz[m * 512 + n]);
        float2 gh = __ldcg((const float2*)&g_Gh[m * 512 + n]);
        float2 h0 = __ldcg((const float2*)&g_h[m * 512 + n]);
        float z0 = sigmoidf_(gz.x), z1 = sigmoidf_(gz.y);
        float hp0 = tanhf(gh.x + q0), hp1 = tanhf(gh.y + q1);
        float hn0 = fminf(fmaxf(fmaf(z0, hp0 - h0.x, h0.x), -5.f), 5.f);
        float hn1 = fminf(fmaxf(fmaf(z1, hp1 - h0.y, h0.y), -5.f), 5.f);
        *(float2*)&g_h[m * 512 + n] = make_float2(hn0, hn1);
        __nv_bfloat162 ph, pl;
        ph.x = __float2bfloat16(hn0); ph.y = __float2bfloat16(hn1);
        pl.x = __float2bfloat16(hn0 - __bfloat162float(ph.x));
        pl.y = __float2bfloat16(hn1 - __bfloat162float(ph.y));
        *(__nv_bfloat162*)&g_hh[m * 512 + n] = ph;
        *(__nv_bfloat162*)&g_hl[m * 512 + n] = pl;
        size_t ho = (size_t)(t - 1) * (B_ * H_) + m * 512 + n;
        *(__nv_bfloat162*)&g_histh[ho] = ph;
        *(__nv_bfloat162*)&g_histl[ho] = pl;
      }
    }
    gbar();
  }
}

// ---------------- final projection: out[:,1..,:] = hist @ Wo + bo (bf16x3 MMA) ----------------
// grid (4, 499); CTA tile [128m x 128n]; warp tile [32m x 64n]; dyn smem 128KB
__global__ void __launch_bounds__(256)
proj_kernel(float* __restrict__ out, const float* __restrict__ bo) {
  extern __shared__ char dsm[];
  const uint32_t sb = smem_u32(dsm);
  const int tid = threadIdx.x, w = tid >> 5, lid = tid & 31;
  const int g = lid >> 2, tig = lid & 3;
  const int by = blockIdx.y;            // hist row block (s index)
  const int n0 = blockIdx.x * 128;
  const int wm = (w & 3) * 32;
  const int wn = (w >> 2) * 64;
  const size_t mbase = (size_t)by * 128;
  float acc[2][8][4] = {};

  #pragma unroll 1
  for (int kc = 0; kc < 8; kc++) {
    if (kc == 0) {
      #pragma unroll
      for (int i = 0; i < 4; i++) {
        int idx = tid + i * 256, r = idx >> 3, c = idx & 7;
        uint32_t sw = swz(r, c);
        size_t eA = (mbase + r) * 512 + c * 8;
        int eB = (n0 + r) * 512 + c * 8;
        cp16(sb + sw, &g_histh[eA]);
        cp16(sb + 16384 + sw, &g_histl[eA]);
        cp16(sb + 32768 + sw, &g_Woth[eB]);
        cp16(sb + 49152 + sw, &g_Wotl[eB]);
      }
      CP_COMMIT();
    }
    if (kc < 7) {
      uint32_t base = sb + ((kc + 1) & 1) * 65536;
      int ko = (kc + 1) * 64;
      #pragma unroll
      for (int i = 0; i < 4; i++) {
        int idx = tid + i * 256, r = idx >> 3, c = idx & 7;
        uint32_t sw = swz(r, c);
        size_t eA = (mbase + r) * 512 + ko + c * 8;
        int eB = (n0 + r) * 512 + ko + c * 8;
        cp16(base + sw, &g_histh[eA]);
        cp16(base + 16384 + sw, &g_histl[eA]);
        cp16(base + 32768 + sw, &g_Woth[eB]);
        cp16(base + 49152 + sw, &g_Wotl[eB]);
      }
      CP_COMMIT();
      CP_WAIT(1);
    } else {
      CP_WAIT(0);
    }
    __syncthreads();
    uint32_t base = sb + (kc & 1) * 65536;
    #pragma unroll
    for (int s = 0; s < 4; s++) {
      int cA = 2 * s + (lid >> 4);
      int cB = 2 * s + ((lid >> 3) & 1);
      uint32_t Ah[2][4], Al[2][4];
      #pragma unroll
      for (int mt = 0; mt < 2; mt++) {
        int rA = wm + mt * 16 + (lid & 15);
        uint32_t aAddr = base + swz(rA, cA);
        lsm4(Ah[mt], aAddr);
        lsm4(Al[mt], aAddr + 16384);
      }
      #pragma unroll
      for (int p = 0; p < 4; p++) {
        int rB = wn + p * 16 + (lid & 7) + ((lid >> 4) << 3);
        uint32_t bAddr = base + 32768 + swz(rB, cB);
        uint32_t Bh[4], Bl[4];
        lsm4(Bh, bAddr);
        lsm4(Bl, bAddr + 16384);
        #pragma unroll
        for (int mt = 0; mt < 2; mt++) {
          mma_bf16(acc[mt][2 * p], Ah[mt], Bh);
          mma_bf16(acc[mt][2 * p], Ah[mt], Bl);
          mma_bf16(acc[mt][2 * p], Al[mt], Bh);
          mma_bf16(acc[mt][2 * p + 1], Ah[mt], Bh + 2);
          mma_bf16(acc[mt][2 * p + 1], Ah[mt], Bl + 2);
          mma_bf16(acc[mt][2 * p + 1], Al[mt], Bh + 2);
        }
      }
    }
    __syncthreads();
  }
  // epilogue: out[b][by+1][n] = v + bo[n]
  #pragma unroll
  for (int mt = 0; mt < 2; mt++) {
    #pragma unroll
    for (int nt = 0; nt < 8; nt++) {
      int n = n0 + wn + nt * 8 + tig * 2;
      float2 bb = *(const float2*)&bo[n];
      #pragma unroll
      for (int rr = 0; rr < 2; rr++) {
        int b = wm + mt * 16 + g + rr * 8;
        float v0 = acc[mt][nt][rr * 2 + 0] + bb.x;
        float v1 = acc[mt][nt][rr * 2 + 1] + bb.y;
        *(float2*)&out[(size_t)b * ((size_t)T_ * D_) + (size_t)(by + 1) * D_ + n] =
            make_float2(v0, v1);
      }
    }
  }
}

// ---------------- setup SIMT GEMM + helpers ----------------
struct EpiFold {
  const float *Ur, *Uz;
  __device__ __forceinline__ void operator()(int m, int n, float v) const {
    if (n < H_)            v += Ur[m * H_ + n];
    else if (n < 2 * H_)   v += Uz[m * H_ + (n - H_)];
    g_Acat[m * NG_ + n] = v;
  }
};
struct EpiStep1 {
  __device__ __forceinline__ void operator()(int m, int n, float v) const {
    v += g_bpack[H_ + n];
    if (n < H_) g_Gz[m * H_ + n] = v;
    else        g_Gh[m * H_ + (n - H_)] = v;
  }
};

template <int BN, class Epi>
__global__ void __launch_bounds__(4 * BN)
gemm_kernel(const float* __restrict__ A, const float* __restrict__ Bm,
            int K, int ldb, Epi epi) {
  constexpr int BM = 32, BK = 32;
  constexpr int NTHR = 4 * BN;
  __shared__ __align__(16) float As[BK][BM + 1];
  __shared__ __align__(16) float Bs[BK][BN];
  const int tid = threadIdx.x;
  const int bm = blockIdx.y * BM;
  const int bn = blockIdx.x * BN;
  const int tx = tid % (BN / 4);
  const int ty = tid / (BN / 4);
  float acc[2][4] = {};
  for (int k0 = 0; k0 < K; k0 += BK) {
    #pragma unroll
    for (int i = tid * 4; i < BM * BK; i += NTHR * 4) {
      int m = i / BK, k = i % BK;
      float4 v = *(const float4*)(A + (size_t)(bm + m) * K + k0 + k);
      As[k + 0][m] = v.x; As[k + 1][m] = v.y; As[k + 2][m] = v.z; As[k + 3][m] = v.w;
    }
    #pragma unroll
    for (int i = tid * 4; i < BK * BN; i += NTHR * 4) {
      int k = i / BN, n = i % BN;
      *(float4*)&Bs[k][n] = *(const float4*)(Bm + (size_t)(k0 + k) * ldb + bn + n);
    }
    __syncthreads();
    #pragma unroll
    for (int kk = 0; kk < BK; kk++) {
      float a0 = As[kk][ty * 2 + 0];
      float a1 = As[kk][ty * 2 + 1];
      float4 b4 = *(float4*)&Bs[kk][tx * 4];
      acc[0][0] = fmaf(a0, b4.x, acc[0][0]);
      acc[0][1] = fmaf(a0, b4.y, acc[0][1]);
      acc[0][2] = fmaf(a0, b4.z, acc[0][2]);
      acc[0][3] = fmaf(a0, b4.w, acc[0][3]);
      acc[1][0] = fmaf(a1, b4.x, acc[1][0]);
      acc[1][1] = fmaf(a1, b4.y, acc[1][1]);
      acc[1][2] = fmaf(a1, b4.z, acc[1][2]);
      acc[1][3] = fmaf(a1, b4.w, acc[1][3]);
    }
    __syncthreads();
  }
  #pragma unroll
  for (int i = 0; i < 2; i++)
    #pragma unroll
    for (int j = 0; j < 4; j++)
      epi(bm + ty * 2 + i, bn + tx * 4 + j, acc[i][j]);
}

__global__ void pack_kernel(const float* __restrict__ Wr, const float* __restrict__ Wz,
                            const float* __restrict__ Wh, const float* __restrict__ br,
                            const float* __restrict__ bz, const float* __restrict__ bh) {
  int idx = blockIdx.x * blockDim.x + threadIdx.x;
  if (idx == 0) g_bar_arrive = 0;
  if (idx < NG_) {
    int sel = idx >> 9, jl = idx & 511;
    g_bpack[idx] = (sel == 0) ? br[jl] : (sel == 1) ? bz[jl] : bh[jl];
  }
  if (idx < D_ * NG_) {
    int d = idx / NG_, j = idx % NG_;
    int sel = j >> 9, jl = j & 511;
    const float* W = (sel == 0) ? Wr : (sel == 1) ? Wz : Wh;
    g_Wpack[idx] = W[d * H_ + jl];
  }
}

__global__ void ccat_kernel(const float* __restrict__ bo) {
  int w = (blockIdx.x * blockDim.x + threadIdx.x) >> 5;
  int lane = threadIdx.x & 31;
  if (w >= NG_) return;
  float acc = 0.f;
  for (int d = lane; d < D_; d += 32)
    acc = fmaf(bo[d], g_Wpack[(size_t)d * NG_ + w], acc);
  #pragma unroll
  for (int o = 16; o; o >>= 1) acc += __shfl_xor_sync(0xffffffffu, acc, o);
  if (lane == 0) g_ccat[w] = acc + g_bpack[w];
}

__global__ void split_kernel(const float* __restrict__ Uh, const float* __restrict__ Wo) {
  int idx = blockIdx.x * blockDim.x + threadIdx.x;
  if (idx < NG_ * H_) {
    int m = idx >> 9, k = idx & 511;
    float x = g_Acat[(size_t)k * NG_ + m];
    __nv_bfloat16 hi = __float2bfloat16(x);
    g_Ath[idx] = hi;
    g_Atl[idx] = __float2bfloat16(x - __bfloat162float(hi));
  }
  if (idx < H_ * H_) {
    int n = idx >> 9, k = idx & 511;
    float x = Uh[(size_t)k * H_ + n];
    __nv_bfloat16 hi = __float2bfloat16(x);
    g_Uth[idx] = hi;
    g_Utl[idx] = __float2bfloat16(x - __bfloat162float(hi));
    float y = Wo[(size_t)k * D_ + n];
    __nv_bfloat16 hi2 = __float2bfloat16(y);
    g_Woth[idx] = hi2;
    g_Wotl[idx] = __float2bfloat16(y - __bfloat162float(hi2));
  }
}

__global__ void copy0_kernel(const float* __restrict__ inputs, float* __restrict__ out) {
  int idx = blockIdx.x * blockDim.x + threadIdx.x;
  if (idx >= B_ * D_) return;
  int b = idx / D_, d = idx % D_;
  out[(size_t)b * ((size_t)T_ * D_) + d] = inputs[idx];
}

__global__ void combine1_kernel() {
  int idx = blockIdx.x * blockDim.x + threadIdx.x;
  if (idx >= B_ * H_) return;
  float z  = sigmoidf_(g_Gz[idx]);
  float hp = tanhf(g_Gh[idx]);
  float hn = fminf(fmaxf(z * hp, -5.f), 5.f);
  g_h[idx] = hn;
  __nv_bfloat16 hi = __float2bfloat16(hn);
  __nv_bfloat16 lo = __float2bfloat16(hn - __bfloat162float(hi));
  g_hh[idx] = hi;
  g_hl[idx] = lo;
  g_histh[idx] = hi;
  g_histl[idx] = lo;
}

// ---------------- launch ----------------
extern "C" void kernel_launch(void* const* d_in, const int* in_sizes, int n_in,
                              void* d_out, int out_size) {
  const float* inputs = (const float*)d_in[0];
  const float* Wz = (const float*)d_in[1];
  const float* Wr = (const float*)d_in[2];
  const float* Wh = (const float*)d_in[3];
  const float* Uz = (const float*)d_in[4];
  const float* Ur = (const float*)d_in[5];
  const float* Uh = (const float*)d_in[6];
  const float* bz = (const float*)d_in[7];
  const float* br = (const float*)d_in[8];
  const float* bh = (const float*)d_in[9];
  const float* Wo = (const float*)d_in[10];
  const float* bo = (const float*)d_in[11];
  float* out = (float*)d_out;

  float* pWpack;
  cudaGetSymbolAddress((void**)&pWpack, g_Wpack);

  cudaFuncSetAttribute(proj_kernel, cudaFuncAttributeMaxDynamicSharedMemorySize, 131072);

  // setup: pack + fold + bf16 splits
  pack_kernel<<<(D_ * NG_ + 255) / 256, 256>>>(Wr, Wz, Wh, br, bz, bh);
  ccat_kernel<<<(NG_ * 32 + 255) / 256, 256>>>(bo);
  gemm_kernel<64, EpiFold><<<dim3(NG_ / 64, H_ / 32), 256>>>(
      Wo, pWpack, D_, NG_, EpiFold{Ur, Uz});
  split_kernel<<<(NG_ * H_ + 255) / 256, 256>>>(Uh, Wo);

  // step 1 (h0 = 0)
  gemm_kernel<64, EpiStep1><<<dim3(1024 / 64, B_ / 32), 256>>>(
      inputs, pWpack + H_, D_, NG_, EpiStep1{});
  combine1_kernel<<<(B_ * H_ + 255) / 256, 256>>>();

  // steps 2..T-1: persistent bf16x3 mma kernel
  recur_kernel<<<NCTA, 256>>>();

  // t = 0 output is the raw input
  copy0_kernel<<<(B_ * D_ + 255) / 256, 256>>>(inputs, out);

  // deferred output projection (bf16x3 mma)
  proj_kernel<<<dim3(4, T_ - 1), 256, 131072>>>(out, bo);
}

// round 7
// speedup vs baseline: 3.2799x; 1.2146x over previous
#include <cuda_runtime.h>
#include <cuda_bf16.h>
#include <math.h>
#include <stdint.h>

#define B_  128
#define D_  512
#define H_  512
#define T_  500
#define NG_ 1536   // 3*H : [r|z|h]
#define NCTA 128

// ---------------- static device scratch ----------------
__device__ float g_Wpack[D_ * NG_];
__device__ float g_bpack[NG_];
__device__ float g_Acat[H_ * NG_];               // [k=512][g=1536] fp32
__device__ float g_ccat[NG_];
__device__ float g_h[B_ * H_];
__device__ float g_Gz[B_ * H_];
__device__ float g_Gh[B_ * H_];
__device__ __nv_bfloat16 g_Ath[NG_ * H_];        // Acat^T hi  [g][k]
__device__ __nv_bfloat16 g_Atl[NG_ * H_];
__device__ __nv_bfloat16 g_Uth[H_ * H_];         // Uh^T hi    [n][k]
__device__ __nv_bfloat16 g_Utl[H_ * H_];
__device__ __nv_bfloat16 g_Woth[H_ * D_];        // Wo^T hi    [n][k]
__device__ __nv_bfloat16 g_Wotl[H_ * D_];
__device__ __nv_bfloat16 g_hh[B_ * H_];          // h split
__device__ __nv_bfloat16 g_hl[B_ * H_];
__device__ __nv_bfloat16 g_rhh[B_ * H_];         // (r*h) split
__device__ __nv_bfloat16 g_rhl[B_ * H_];
__device__ __nv_bfloat16 g_histh[(size_t)(T_ - 1) * B_ * H_];
__device__ __nv_bfloat16 g_histl[(size_t)(T_ - 1) * B_ * H_];

__device__ unsigned g_bar_arrive = 0;
__device__ unsigned g_bar_gen = 0;

__device__ __forceinline__ float sigmoidf_(float x) { return 1.f / (1.f + __expf(-x)); }

__device__ __forceinline__ void gbar() {
  __syncthreads();
  if (threadIdx.x == 0) {
    __threadfence();
    unsigned gen = *(volatile unsigned*)&g_bar_gen;
    if (atomicAdd(&g_bar_arrive, 1u) == NCTA - 1) {
      g_bar_arrive = 0;
      __threadfence();
      *(volatile unsigned*)&g_bar_gen = gen + 1;
    } else {
      while (*(volatile unsigned*)&g_bar_gen == gen) {}
    }
    __threadfence();
  }
  __syncthreads();
}

// ---------------- mma.sync / ldmatrix / cp.async primitives (sm_80 PTX) ----------------
__device__ __forceinline__ uint32_t smem_u32(const void* p) {
  uint32_t a;
  asm("{ .reg .u64 t; cvta.to.shared.u64 t, %1; cvt.u32.u64 %0, t; }" : "=r"(a) : "l"(p));
  return a;
}
__device__ __forceinline__ void cp16(uint32_t dst, const void* src) {
  asm volatile("cp.async.cg.shared.global [%0], [%1], 16;" :: "r"(dst), "l"(src));
}
#define CP_COMMIT() asm volatile("cp.async.commit_group;" ::: "memory")
#define CP_WAIT(n)  asm volatile("cp.async.wait_group %0;" :: "n"(n) : "memory")
__device__ __forceinline__ void lsm4(uint32_t* r, uint32_t a) {
  asm volatile("ldmatrix.sync.aligned.m8n8.x4.shared.b16 {%0,%1,%2,%3}, [%4];"
               : "=r"(r[0]), "=r"(r[1]), "=r"(r[2]), "=r"(r[3]) : "r"(a));
}
__device__ __forceinline__ void lsm2(uint32_t* r, uint32_t a) {
  asm volatile("ldmatrix.sync.aligned.m8n8.x2.shared.b16 {%0,%1}, [%2];"
               : "=r"(r[0]), "=r"(r[1]) : "r"(a));
}
__device__ __forceinline__ void mma_bf16(float* d, const uint32_t* a, const uint32_t* b) {
  asm volatile(
      "mma.sync.aligned.m16n8k16.row.col.f32.bf16.bf16.f32 "
      "{%0,%1,%2,%3}, {%4,%5,%6,%7}, {%8,%9}, {%0,%1,%2,%3};"
      : "+f"(d[0]), "+f"(d[1]), "+f"(d[2]), "+f"(d[3])
      : "r"(a[0]), "r"(a[1]), "r"(a[2]), "r"(a[3]), "r"(b[0]), "r"(b[1]));
}
// row pitch 1024B (512 bf16); 16B-chunk swizzle
__device__ __forceinline__ uint32_t swz(int r, int c) {
  return (uint32_t)(r * 1024 + (((c) ^ (r & 7)) << 4));
}
// 128B-pitch swizzle for proj kernel tiles
__device__ __forceinline__ uint32_t swz128(int r, int c) {
  return (uint32_t)(r * 128 + ((c ^ (r & 7)) << 4));
}

// smem offsets for recur kernel (dynamic, 192 KB)
#define WA_HI  0u
#define WA_LO  49152u
#define WB_HI  98304u
#define WB_LO  114688u
#define ACT_HI 131072u
#define ACT_LO 163840u
#define RSMEM  196608

// ---------------- persistent recurrence kernel: 128 CTAs x 128 thr ----------------
// Weights live in smem for all steps. Per step:
//  Stage A: C[m=128 batch, n=1536 gates] = h @ Acat ; CTA tile m32 x n48 (4m x 32n)
//  Stage B: C[128 x 512] = rh @ Uh ; CTA tile m32 x n16 (4m x 32n), gating epilogue
__global__ void __launch_bounds__(128)
recur_kernel() {
  extern __shared__ char smem[];
  const uint32_t sb = smem_u32(smem);
  const int tid = threadIdx.x, bid = blockIdx.x;
  const int w = tid >> 5, lid = tid & 31;
  const int g = lid >> 2, tig = lid & 3;
  const int m0 = (bid & 3) * 32;
  const int n0A = (bid >> 2) * 48;
  const int n0B = (bid >> 2) * 16;
  const int wm = (w & 1) * 16;
  const int wnA = (w >> 1) * 24;
  const int wnB = (w >> 1) * 8;
  const int rA = wm + (lid & 15);                 // act ldmatrix row
  const int rB16 = (lid & 7) + ((lid >> 4) << 3); // + wn at use
  const int rB8 = lid & 7;
  const int cA = lid >> 4;
  const int cSel = (lid >> 3) & 1;

  // ---- one-time: load weight strips into smem ----
  #pragma unroll
  for (int i = 0; i < 24; i++) {
    int idx = tid + i * 128, r = idx >> 6, c = idx & 63;
    size_t go = (size_t)(n0A + r) * 512 + c * 8;
    cp16(sb + WA_HI + swz(r, c), &g_Ath[go]);
    cp16(sb + WA_LO + swz(r, c), &g_Atl[go]);
  }
  #pragma unroll
  for (int i = 0; i < 8; i++) {
    int idx = tid + i * 128, r = idx >> 6, c = idx & 63;
    size_t go = (size_t)(n0B + r) * 512 + c * 8;
    cp16(sb + WB_HI + swz(r, c), &g_Uth[go]);
    cp16(sb + WB_LO + swz(r, c), &g_Utl[go]);
  }
  CP_COMMIT();
  CP_WAIT(0);
  __syncthreads();

  for (int t = 2; t < T_; t++) {
    // ================= Stage A =================
    {
      // issue all 4 act chunk loads (disjoint regions, 4 commit groups)
      #pragma unroll
      for (int kc = 0; kc < 4; kc++) {
        #pragma unroll
        for (int i = 0; i < 4; i++) {
          int idx = tid + i * 128, r = idx >> 4, cs = idx & 15;
          int go = (m0 + r) * 512 + kc * 128 + cs * 8;
          cp16(sb + ACT_HI + swz(r, kc * 16 + cs), &g_hh[go]);
          cp16(sb + ACT_LO + swz(r, kc * 16 + cs), &g_hl[go]);
        }
        CP_COMMIT();
      }
      float acc0[4] = {}, acc1[4] = {}, acc2[4] = {};
      #pragma unroll
      for (int kc = 0; kc < 4; kc++) {
        if (kc == 0)      CP_WAIT(3);
        else if (kc == 1) CP_WAIT(2);
        else if (kc == 2) CP_WAIT(1);
        else              CP_WAIT(0);
        __syncthreads();
        #pragma unroll
        for (int s = 0; s < 8; s++) {
          int ks = kc * 8 + s;
          uint32_t Ah[4], Al[4], Bh[4], Bl[4], Bh2[2], Bl2[2];
          uint32_t ao = swz(rA, ks * 2 + cA);
          lsm4(Ah, sb + ACT_HI + ao);
          lsm4(Al, sb + ACT_LO + ao);
          uint32_t bo = swz(wnA + rB16, ks * 2 + cSel);
          lsm4(Bh, sb + WA_HI + bo);
          lsm4(Bl, sb + WA_LO + bo);
          uint32_t bo2 = swz(wnA + 16 + rB8, ks * 2 + cSel);
          lsm2(Bh2, sb + WA_HI + bo2);
          lsm2(Bl2, sb + WA_LO + bo2);
          mma_bf16(acc0, Ah, Bh);     mma_bf16(acc0, Ah, Bl);     mma_bf16(acc0, Al, Bh);
          mma_bf16(acc1, Ah, Bh + 2); mma_bf16(acc1, Ah, Bl + 2); mma_bf16(acc1, Al, Bh + 2);
          mma_bf16(acc2, Ah, Bh2);    mma_bf16(acc2, Ah, Bl2);    mma_bf16(acc2, Al, Bh2);
        }
      }
      // epilogue: 3 n8-tiles
      const int m1 = m0 + wm + g, m2 = m1 + 8;
      #pragma unroll
      for (int j = 0; j < 3; j++) {
        float* a = (j == 0) ? acc0 : (j == 1) ? acc1 : acc2;
        int n = n0A + wnA + j * 8 + tig * 2;
        float2 cc = *(const float2*)&g_ccat[n];
        float v00 = a[0] + cc.x, v01 = a[1] + cc.y;
        float v10 = a[2] + cc.x, v11 = a[3] + cc.y;
        if (n < 512) {            // r gates -> rh split
          int u = n;
          float2 hA = __ldcg((const float2*)&g_h[m1 * 512 + u]);
          float2 hB = __ldcg((const float2*)&g_h[m2 * 512 + u]);
          float rh00 = sigmoidf_(v00) * hA.x, rh01 = sigmoidf_(v01) * hA.y;
          float rh10 = sigmoidf_(v10) * hB.x, rh11 = sigmoidf_(v11) * hB.y;
          __nv_bfloat162 ph, pl;
          ph.x = __float2bfloat16(rh00); ph.y = __float2bfloat16(rh01);
          pl.x = __float2bfloat16(rh00 - __bfloat162float(ph.x));
          pl.y = __float2bfloat16(rh01 - __bfloat162float(ph.y));
          *(__nv_bfloat162*)&g_rhh[m1 * 512 + u] = ph;
          *(__nv_bfloat162*)&g_rhl[m1 * 512 + u] = pl;
          ph.x = __float2bfloat16(rh10); ph.y = __float2bfloat16(rh11);
          pl.x = __float2bfloat16(rh10 - __bfloat162float(ph.x));
          pl.y = __float2bfloat16(rh11 - __bfloat162float(ph.y));
          *(__nv_bfloat162*)&g_rhh[m2 * 512 + u] = ph;
          *(__nv_bfloat162*)&g_rhl[m2 * 512 + u] = pl;
        } else if (n < 1024) {    // z preacts
          int u = n - 512;
          *(float2*)&g_Gz[m1 * 512 + u] = make_float2(v00, v01);
          *(float2*)&g_Gz[m2 * 512 + u] = make_float2(v10, v11);
        } else {                  // h preacts
          int u = n - 1024;
          *(float2*)&g_Gh[m1 * 512 + u] = make_float2(v00, v01);
          *(float2*)&g_Gh[m2 * 512 + u] = make_float2(v10, v11);
        }
      }
    }
    gbar();

    // ================= Stage B =================
    {
      #pragma unroll
      for (int kc = 0; kc < 4; kc++) {
        #pragma unroll
        for (int i = 0; i < 4; i++) {
          int idx = tid + i * 128, r = idx >> 4, cs = idx & 15;
          int go = (m0 + r) * 512 + kc * 128 + cs * 8;
          cp16(sb + ACT_HI + swz(r, kc * 16 + cs), &g_rhh[go]);
          cp16(sb + ACT_LO + swz(r, kc * 16 + cs), &g_rhl[go]);
        }
        CP_COMMIT();
      }
      float acc[4] = {};
      #pragma unroll
      for (int kc = 0; kc < 4; kc++) {
        if (kc == 0)      CP_WAIT(3);
        else if (kc == 1) CP_WAIT(2);
        else if (kc == 2) CP_WAIT(1);
        else              CP_WAIT(0);
        __syncthreads();
        #pragma unroll
        for (int s = 0; s < 8; s++) {
          int ks = kc * 8 + s;
          uint32_t Ah[4], Al[4], Bh2[2], Bl2[2];
          uint32_t ao = swz(rA, ks * 2 + cA);
          lsm4(Ah, sb + ACT_HI + ao);
          lsm4(Al, sb + ACT_LO + ao);
          uint32_t bo = swz(wnB + rB8, ks * 2 + cSel);
          lsm2(Bh2, sb + WB_HI + bo);
          lsm2(Bl2, sb + WB_LO + bo);
          mma_bf16(acc, Ah, Bh2);
          mma_bf16(acc, Ah, Bl2);
          mma_bf16(acc, Al, Bh2);
        }
      }
      // gating epilogue
      const int n = n0B + wnB + tig * 2;
      const int m1 = m0 + wm + g;
      #pragma unroll
      for (int rr = 0; rr < 2; rr++) {
        int m = m1 + rr * 8;
        float q0 = acc[rr * 2 + 0], q1 = acc[rr * 2 + 1];
        float2 gz = __ldcg((const float2*)&g_Gz[m * 512 + n]);
        float2 gh = __ldcg((const float2*)&g_Gh[m * 512 + n]);
        float2 h0 = __ldcg((const float2*)&g_h[m * 512 + n]);
        float z0 = sigmoidf_(gz.x), z1 = sigmoidf_(gz.y);
        float hp0 = tanhf(gh.x + q0), hp1 = tanhf(gh.y + q1);
        float hn0 = fminf(fmaxf(fmaf(z0, hp0 - h0.x, h0.x), -5.f), 5.f);
        float hn1 = fminf(fmaxf(fmaf(z1, hp1 - h0.y, h0.y), -5.f), 5.f);
        *(float2*)&g_h[m * 512 + n] = make_float2(hn0, hn1);
        __nv_bfloat162 ph, pl;
        ph.x = __float2bfloat16(hn0); ph.y = __float2bfloat16(hn1);
        pl.x = __float2bfloat16(hn0 - __bfloat162float(ph.x));
        pl.y = __float2bfloat16(hn1 - __bfloat162float(ph.y));
        *(__nv_bfloat162*)&g_hh[m * 512 + n] = ph;
        *(__nv_bfloat162*)&g_hl[m * 512 + n] = pl;
        size_t ho = (size_t)(t - 1) * (B_ * H_) + m * 512 + n;
        *(__nv_bfloat162*)&g_histh[ho] = ph;
        *(__nv_bfloat162*)&g_histl[ho] = pl;
      }
    }
    gbar();
  }
}

// ---------------- final projection: out[:,1..,:] = hist @ Wo + bo (bf16x3 MMA) ----------------
__global__ void __launch_bounds__(256)
proj_kernel(float* __restrict__ out, const float* __restrict__ bo) {
  extern __shared__ char dsm[];
  const uint32_t sb = smem_u32(dsm);
  const int tid = threadIdx.x, w = tid >> 5, lid = tid & 31;
  const int g = lid >> 2, tig = lid & 3;
  const int by = blockIdx.y;
  const int n0 = blockIdx.x * 128;
  const int wm = (w & 3) * 32;
  const int wn = (w >> 2) * 64;
  const size_t mbase = (size_t)by * 128;
  float acc[2][8][4] = {};

  #pragma unroll 1
  for (int kc = 0; kc < 8; kc++) {
    if (kc == 0) {
      #pragma unroll
      for (int i = 0; i < 4; i++) {
        int idx = tid + i * 256, r = idx >> 3, c = idx & 7;
        uint32_t sw = swz128(r, c);
        size_t eA = (mbase + r) * 512 + c * 8;
        int eB = (n0 + r) * 512 + c * 8;
        cp16(sb + sw, &g_histh[eA]);
        cp16(sb + 16384 + sw, &g_histl[eA]);
        cp16(sb + 32768 + sw, &g_Woth[eB]);
        cp16(sb + 49152 + sw, &g_Wotl[eB]);
      }
      CP_COMMIT();
    }
    if (kc < 7) {
      uint32_t base = sb + ((kc + 1) & 1) * 65536;
      int ko = (kc + 1) * 64;
      #pragma unroll
      for (int i = 0; i < 4; i++) {
        int idx = tid + i * 256, r = idx >> 3, c = idx & 7;
        uint32_t sw = swz128(r, c);
        size_t eA = (mbase + r) * 512 + ko + c * 8;
        int eB = (n0 + r) * 512 + ko + c * 8;
        cp16(base + sw, &g_histh[eA]);
        cp16(base + 16384 + sw, &g_histl[eA]);
        cp16(base + 32768 + sw, &g_Woth[eB]);
        cp16(base + 49152 + sw, &g_Wotl[eB]);
      }
      CP_COMMIT();
      CP_WAIT(1);
    } else {
      CP_WAIT(0);
    }
    __syncthreads();
    uint32_t base = sb + (kc & 1) * 65536;
    #pragma unroll
    for (int s = 0; s < 4; s++) {
      int cA = 2 * s + (lid >> 4);
      int cB = 2 * s + ((lid >> 3) & 1);
      uint32_t Ah[2][4], Al[2][4];
      #pragma unroll
      for (int mt = 0; mt < 2; mt++) {
        int rA = wm + mt * 16 + (lid & 15);
        uint32_t aAddr = base + swz128(rA, cA);
        lsm4(Ah[mt], aAddr);
        lsm4(Al[mt], aAddr + 16384);
      }
      #pragma unroll
      for (int p = 0; p < 4; p++) {
        int rB = wn + p * 16 + (lid & 7) + ((lid >> 4) << 3);
        uint32_t bAddr = base + 32768 + swz128(rB, cB);
        uint32_t Bh[4], Bl[4];
        lsm4(Bh, bAddr);
        lsm4(Bl, bAddr + 16384);
        #pragma unroll
        for (int mt = 0; mt < 2; mt++) {
          mma_bf16(acc[mt][2 * p], Ah[mt], Bh);
          mma_bf16(acc[mt][2 * p], Ah[mt], Bl);
          mma_bf16(acc[mt][2 * p], Al[mt], Bh);
          mma_bf16(acc[mt][2 * p + 1], Ah[mt], Bh + 2);
          mma_bf16(acc[mt][2 * p + 1], Ah[mt], Bl + 2);
          mma_bf16(acc[mt][2 * p + 1], Al[mt], Bh + 2);
        }
      }
    }
    __syncthreads();
  }
  #pragma unroll
  for (int mt = 0; mt < 2; mt++) {
    #pragma unroll
    for (int nt = 0; nt < 8; nt++) {
      int n = n0 + wn + nt * 8 + tig * 2;
      float2 bb = *(const float2*)&bo[n];
      #pragma unroll
      for (int rr = 0; rr < 2; rr++) {
        int b = wm + mt * 16 + g + rr * 8;
        float v0 = acc[mt][nt][rr * 2 + 0] + bb.x;
        float v1 = acc[mt][nt][rr * 2 + 1] + bb.y;
        *(float2*)&out[(size_t)b * ((size_t)T_ * D_) + (size_t)(by + 1) * D_ + n] =
            make_float2(v0, v1);
      }
    }
  }
}

// ---------------- setup SIMT GEMM + helpers ----------------
struct EpiFold {
  const float *Ur, *Uz;
  __device__ __forceinline__ void operator()(int m, int n, float v) const {
    if (n < H_)            v += Ur[m * H_ + n];
    else if (n < 2 * H_)   v += Uz[m * H_ + (n - H_)];
    g_Acat[m * NG_ + n] = v;
  }
};
struct EpiStep1 {
  __device__ __forceinline__ void operator()(int m, int n, float v) const {
    v += g_bpack[H_ + n];
    if (n < H_) g_Gz[m * H_ + n] = v;
    else        g_Gh[m * H_ + (n - H_)] = v;
  }
};

template <int BN, class Epi>
__global__ void __launch_bounds__(4 * BN)
gemm_kernel(const float* __restrict__ A, const float* __restrict__ Bm,
            int K, int ldb, Epi epi) {
  constexpr int BM = 32, BK = 32;
  constexpr int NTHR = 4 * BN;
  __shared__ __align__(16) float As[BK][BM + 1];
  __shared__ __align__(16) float Bs[BK][BN];
  const int tid = threadIdx.x;
  const int bm = blockIdx.y * BM;
  const int bn = blockIdx.x * BN;
  const int tx = tid % (BN / 4);
  const int ty = tid / (BN / 4);
  float acc[2][4] = {};
  for (int k0 = 0; k0 < K; k0 += BK) {
    #pragma unroll
    for (int i = tid * 4; i < BM * BK; i += NTHR * 4) {
      int m = i / BK, k = i % BK;
      float4 v = *(const float4*)(A + (size_t)(bm + m) * K + k0 + k);
      As[k + 0][m] = v.x; As[k + 1][m] = v.y; As[k + 2][m] = v.z; As[k + 3][m] = v.w;
    }
    #pragma unroll
    for (int i = tid * 4; i < BK * BN; i += NTHR * 4) {
      int k = i / BN, n = i % BN;
      *(float4*)&Bs[k][n] = *(const float4*)(Bm + (size_t)(k0 + k) * ldb + bn + n);
    }
    __syncthreads();
    #pragma unroll
    for (int kk = 0; kk < BK; kk++) {
      float a0 = As[kk][ty * 2 + 0];
      float a1 = As[kk][ty * 2 + 1];
      float4 b4 = *(float4*)&Bs[kk][tx * 4];
      acc[0][0] = fmaf(a0, b4.x, acc[0][0]);
      acc[0][1] = fmaf(a0, b4.y, acc[0][1]);
      acc[0][2] = fmaf(a0, b4.z, acc[0][2]);
      acc[0][3] = fmaf(a0, b4.w, acc[0][3]);
      acc[1][0] = fmaf(a1, b4.x, acc[1][0]);
      acc[1][1] = fmaf(a1, b4.y, acc[1][1]);
      acc[1][2] = fmaf(a1, b4.z, acc[1][2]);
      acc[1][3] = fmaf(a1, b4.w, acc[1][3]);
    }
    __syncthreads();
  }
  #pragma unroll
  for (int i = 0; i < 2; i++)
    #pragma unroll
    for (int j = 0; j < 4; j++)
      epi(bm + ty * 2 + i, bn + tx * 4 + j, acc[i][j]);
}

__global__ void pack_kernel(const float* __restrict__ Wr, const float* __restrict__ Wz,
                            const float* __restrict__ Wh, const float* __restrict__ br,
                            const float* __restrict__ bz, const float* __restrict__ bh) {
  int idx = blockIdx.x * blockDim.x + threadIdx.x;
  if (idx == 0) g_bar_arrive = 0;
  if (idx < NG_) {
    int sel = idx >> 9, jl = idx & 511;
    g_bpack[idx] = (sel == 0) ? br[jl] : (sel == 1) ? bz[jl] : bh[jl];
  }
  if (idx < D_ * NG_) {
    int d = idx / NG_, j = idx % NG_;
    int sel = j >> 9, jl = j & 511;
    const float* W = (sel == 0) ? Wr : (sel == 1) ? Wz : Wh;
    g_Wpack[idx] = W[d * H_ + jl];
  }
}

__global__ void ccat_kernel(const float* __restrict__ bo) {
  int w = (blockIdx.x * blockDim.x + threadIdx.x) >> 5;
  int lane = threadIdx.x & 31;
  if (w >= NG_) return;
  float acc = 0.f;
  for (int d = lane; d < D_; d += 32)
    acc = fmaf(bo[d], g_Wpack[(size_t)d * NG_ + w], acc);
  #pragma unroll
  for (int o = 16; o; o >>= 1) acc += __shfl_xor_sync(0xffffffffu, acc, o);
  if (lane == 0) g_ccat[w] = acc + g_bpack[w];
}

__global__ void split_kernel(const float* __restrict__ Uh, const float* __restrict__ Wo) {
  int idx = blockIdx.x * blockDim.x + threadIdx.x;
  if (idx < NG_ * H_) {
    int m = idx >> 9, k = idx & 511;
    float x = g_Acat[(size_t)k * NG_ + m];
    __nv_bfloat16 hi = __float2bfloat16(x);
    g_Ath[idx] = hi;
    g_Atl[idx] = __float2bfloat16(x - __bfloat162float(hi));
  }
  if (idx < H_ * H_) {
    int n = idx >> 9, k = idx & 511;
    float x = Uh[(size_t)k * H_ + n];
    __nv_bfloat16 hi = __float2bfloat16(x);
    g_Uth[idx] = hi;
    g_Utl[idx] = __float2bfloat16(x - __bfloat162float(hi));
    float y = Wo[(size_t)k * D_ + n];
    __nv_bfloat16 hi2 = __float2bfloat16(y);
    g_Woth[idx] = hi2;
    g_Wotl[idx] = __float2bfloat16(y - __bfloat162float(hi2));
  }
}

__global__ void copy0_kernel(const float* __restrict__ inputs, float* __restrict__ out) {
  int idx = blockIdx.x * blockDim.x + threadIdx.x;
  if (idx >= B_ * D_) return;
  int b = idx / D_, d = idx % D_;
  out[(size_t)b * ((size_t)T_ * D_) + d] = inputs[idx];
}

__global__ void combine1_kernel() {
  int idx = blockIdx.x * blockDim.x + threadIdx.x;
  if (idx >= B_ * H_) return;
  float z  = sigmoidf_(g_Gz[idx]);
  float hp = tanhf(g_Gh[idx]);
  float hn = fminf(fmaxf(z * hp, -5.f), 5.f);
  g_h[idx] = hn;
  __nv_bfloat16 hi = __float2bfloat16(hn);
  __nv_bfloat16 lo = __float2bfloat16(hn - __bfloat162float(hi));
  g_hh[idx] = hi;
  g_hl[idx] = lo;
  g_histh[idx] = hi;
  g_histl[idx] = lo;
}

// ---------------- launch ----------------
extern "C" void kernel_launch(void* const* d_in, const int* in_sizes, int n_in,
                              void* d_out, int out_size) {
  const float* inputs = (const float*)d_in[0];
  const float* Wz = (const float*)d_in[1];
  const float* Wr = (const float*)d_in[2];
  const float* Wh = (const float*)d_in[3];
  const float* Uz = (const float*)d_in[4];
  const float* Ur = (const float*)d_in[5];
  const float* Uh = (const float*)d_in[6];
  const float* bz = (const float*)d_in[7];
  const float* br = (const float*)d_in[8];
  const float* bh = (const float*)d_in[9];
  const float* Wo = (const float*)d_in[10];
  const float* bo = (const float*)d_in[11];
  float* out = (float*)d_out;

  float* pWpack;
  cudaGetSymbolAddress((void**)&pWpack, g_Wpack);

  cudaFuncSetAttribute(proj_kernel, cudaFuncAttributeMaxDynamicSharedMemorySize, 131072);
  cudaFuncSetAttribute(recur_kernel, cudaFuncAttributeMaxDynamicSharedMemorySize, RSMEM);

  // setup: pack + fold + bf16 splits
  pack_kernel<<<(D_ * NG_ + 255) / 256, 256>>>(Wr, Wz, Wh, br, bz, bh);
  ccat_kernel<<<(NG_ * 32 + 255) / 256, 256>>>(bo);
  gemm_kernel<64, EpiFold><<<dim3(NG_ / 64, H_ / 32), 256>>>(
      Wo, pWpack, D_, NG_, EpiFold{Ur, Uz});
  split_kernel<<<(NG_ * H_ + 255) / 256, 256>>>(Uh, Wo);

  // step 1 (h0 = 0)
  gemm_kernel<64, EpiStep1><<<dim3(1024 / 64, B_ / 32), 256>>>(
      inputs, pWpack + H_, D_, NG_, EpiStep1{});
  combine1_kernel<<<(B_ * H_ + 255) / 256, 256>>>();

  // steps 2..T-1: persistent bf16x3 mma kernel, weights smem-resident
  recur_kernel<<<NCTA, 128, RSMEM>>>();

  // t = 0 output is the raw input
  copy0_kernel<<<(B_ * D_ + 255) / 256, 256>>>(inputs, out);

  // deferred output projection (bf16x3 mma)
  proj_kernel<<<dim3(4, T_ - 1), 256, 131072>>>(out, bo);
}

// round 8
// speedup vs baseline: 3.7439x; 1.1415x over previous
#include <cuda_runtime.h>
#include <cuda_bf16.h>
#include <math.h>
#include <stdint.h>

#define B_  128
#define D_  512
#define H_  512
#define T_  500
#define NG_ 1536   // 3*H : [r|z|h]
#define NCTA 128

// ---------------- static device scratch ----------------
__device__ float g_Wpack[D_ * NG_];
__device__ float g_bpack[NG_];
__device__ float g_Acat[H_ * NG_];               // [k=512][g=1536] fp32
__device__ float g_ccat[NG_];
__device__ float g_h[B_ * H_];
__device__ float g_Gz[B_ * H_];
__device__ float g_Gh[B_ * H_];
__device__ __nv_bfloat16 g_Ath[NG_ * H_];        // Acat^T hi  [g][k]
__device__ __nv_bfloat16 g_Atl[NG_ * H_];
__device__ __nv_bfloat16 g_Uth[H_ * H_];         // Uh^T hi    [n][k]
__device__ __nv_bfloat16 g_Utl[H_ * H_];
__device__ __nv_bfloat16 g_Woth[H_ * D_];        // Wo^T hi    [n][k]
__device__ __nv_bfloat16 g_Wotl[H_ * D_];
__device__ __nv_bfloat16 g_hh[B_ * H_];          // h split
__device__ __nv_bfloat16 g_hl[B_ * H_];
__device__ __nv_bfloat16 g_rhh[B_ * H_];         // (r*h) split
__device__ __nv_bfloat16 g_rhl[B_ * H_];
__device__ __nv_bfloat16 g_histh[(size_t)(T_ - 1) * B_ * H_];
__device__ __nv_bfloat16 g_histl[(size_t)(T_ - 1) * B_ * H_];

__device__ unsigned g_bar_arrive = 0;
__device__ unsigned g_bar_gen = 0;

__device__ __forceinline__ float sigmoidf_(float x) { return 1.f / (1.f + __expf(-x)); }

__device__ __forceinline__ void gbar() {
  __syncthreads();
  if (threadIdx.x == 0) {
    __threadfence();
    unsigned gen = *(volatile unsigned*)&g_bar_gen;
    if (atomicAdd(&g_bar_arrive, 1u) == NCTA - 1) {
      g_bar_arrive = 0;
      __threadfence();
      *(volatile unsigned*)&g_bar_gen = gen + 1;
    } else {
      while (*(volatile unsigned*)&g_bar_gen == gen) {}
    }
    __threadfence();
  }
  __syncthreads();
}

// ---------------- mma.sync / ldmatrix / cp.async primitives (sm_80 PTX) ----------------
__device__ __forceinline__ uint32_t smem_u32(const void* p) {
  uint32_t a;
  asm("{ .reg .u64 t; cvta.to.shared.u64 t, %1; cvt.u32.u64 %0, t; }" : "=r"(a) : "l"(p));
  return a;
}
__device__ __forceinline__ void cp16(uint32_t dst, const void* src) {
  asm volatile("cp.async.cg.shared.global [%0], [%1], 16;" :: "r"(dst), "l"(src));
}
#define CP_COMMIT() asm volatile("cp.async.commit_group;" ::: "memory")
#define CP_WAIT(n)  asm volatile("cp.async.wait_group %0;" :: "n"(n) : "memory")
#define NB_SYNC(id) asm volatile("bar.sync %0, 128;" :: "r"(id) : "memory")
__device__ __forceinline__ void lsm4(uint32_t* r, uint32_t a) {
  asm volatile("ldmatrix.sync.aligned.m8n8.x4.shared.b16 {%0,%1,%2,%3}, [%4];"
               : "=r"(r[0]), "=r"(r[1]), "=r"(r[2]), "=r"(r[3]) : "r"(a));
}
__device__ __forceinline__ void lsm2(uint32_t* r, uint32_t a) {
  asm volatile("ldmatrix.sync.aligned.m8n8.x2.shared.b16 {%0,%1}, [%2];"
               : "=r"(r[0]), "=r"(r[1]) : "r"(a));
}
__device__ __forceinline__ void mma_bf16(float* d, const uint32_t* a, const uint32_t* b) {
  asm volatile(
      "mma.sync.aligned.m16n8k16.row.col.f32.bf16.bf16.f32 "
      "{%0,%1,%2,%3}, {%4,%5,%6,%7}, {%8,%9}, {%0,%1,%2,%3};"
      : "+f"(d[0]), "+f"(d[1]), "+f"(d[2]), "+f"(d[3])
      : "r"(a[0]), "r"(a[1]), "r"(a[2]), "r"(a[3]), "r"(b[0]), "r"(b[1]));
}
// row pitch 1024B (512 bf16); 16B-chunk swizzle
__device__ __forceinline__ uint32_t swz(int r, int c) {
  return (uint32_t)(r * 1024 + (((c) ^ (r & 7)) << 4));
}
// 128B-pitch swizzle for proj kernel tiles
__device__ __forceinline__ uint32_t swz128(int r, int c) {
  return (uint32_t)(r * 128 + ((c ^ (r & 7)) << 4));
}

// smem offsets for recur kernel (dynamic, 200 KB)
#define WA_HI  0u
#define WA_LO  49152u
#define WB_HI  98304u
#define WB_LO  114688u
#define ACT_HI 131072u
#define ACT_LO 163840u
#define SCR_   196608u
#define RSMEM  204800

// ---------------- persistent recurrence kernel: 128 CTAs x 256 thr ----------------
// Weights smem-resident. Warp-level K-split: warps 0-3 do K[0,256), 4-7 do K[256,512).
//  Stage A: C[128,1536] = h @ Acat ; CTA tile m32 x n48
//  Stage B: C[128,512]  = rh @ Uh ; CTA tile m32 x n16, gating epilogue
__global__ void __launch_bounds__(256)
recur_kernel() {
  extern __shared__ char smem[];
  const uint32_t sb = smem_u32(smem);
  float* scr = (float*)(smem + SCR_);
  const int tid = threadIdx.x, bid = blockIdx.x;
  const int w = tid >> 5, lid = tid & 31;
  const int g = lid >> 2, tig = lid & 3;
  const int wpos = w & 3, wk = w >> 2;
  const int m0 = (bid & 3) * 32;
  const int n0A = (bid >> 2) * 48;
  const int n0B = (bid >> 2) * 16;
  const int wm = (wpos & 1) * 16;
  const int wnA = (wpos >> 1) * 24;
  const int wnB = (wpos >> 1) * 8;
  const int rA = wm + (lid & 15);
  const int rB16 = (lid & 7) + ((lid >> 4) << 3);
  const int rB8 = lid & 7;
  const int cA = lid >> 4;
  const int cSel = (lid >> 3) & 1;
  const int m1 = m0 + wm + g, m2 = m1 + 8;
  const int half = tid >> 7, ltid = tid & 127;

  // ---- one-time: load weight strips into smem ----
  #pragma unroll
  for (int i = 0; i < 12; i++) {
    int idx = tid + i * 256, r = idx >> 6, c = idx & 63;
    size_t go = (size_t)(n0A + r) * 512 + c * 8;
    cp16(sb + WA_HI + swz(r, c), &g_Ath[go]);
    cp16(sb + WA_LO + swz(r, c), &g_Atl[go]);
  }
  #pragma unroll
  for (int i = 0; i < 4; i++) {
    int idx = tid + i * 256, r = idx >> 6, c = idx & 63;
    size_t go = (size_t)(n0B + r) * 512 + c * 8;
    cp16(sb + WB_HI + swz(r, c), &g_Uth[go]);
    cp16(sb + WB_LO + swz(r, c), &g_Utl[go]);
  }
  CP_COMMIT();
  CP_WAIT(0);
  __syncthreads();

  for (int t = 2; t < T_; t++) {
    // ================= Stage A =================
    {
      // prefetch epilogue h (r-strips, warps 0-3) — hides behind MMA loop
      float2 phA[3][2];
      if (w < 4 && n0A < 512) {
        #pragma unroll
        for (int j = 0; j < 3; j++) {
          int n = n0A + wnA + j * 8 + tig * 2;
          int u = n & 511;
          phA[j][0] = __ldcg((const float2*)&g_h[m1 * 512 + u]);
          phA[j][1] = __ldcg((const float2*)&g_h[m2 * 512 + u]);
        }
      }
      // act loads: half 0 loads chunks 0,1 ; half 1 loads chunks 2,3
      #pragma unroll
      for (int kc2 = 0; kc2 < 2; kc2++) {
        int kc = half * 2 + kc2;
        #pragma unroll
        for (int i = 0; i < 4; i++) {
          int idx = ltid + i * 128, r = idx >> 4, cs = idx & 15;
          int go = (m0 + r) * 512 + kc * 128 + cs * 8;
          cp16(sb + ACT_HI + swz(r, kc * 16 + cs), &g_hh[go]);
          cp16(sb + ACT_LO + swz(r, kc * 16 + cs), &g_hl[go]);
        }
        CP_COMMIT();
      }
      float acc0[4] = {}, acc1[4] = {}, acc2[4] = {};
      #pragma unroll
      for (int kc2 = 0; kc2 < 2; kc2++) {
        if (kc2 == 0) CP_WAIT(1); else CP_WAIT(0);
        NB_SYNC(1 + wk);
        #pragma unroll
        for (int s = 0; s < 8; s++) {
          int ks = (wk * 2 + kc2) * 8 + s;
          uint32_t Ah[4], Al[4], Bh[4], Bl[4], Bh2[2], Bl2[2];
          uint32_t ao = swz(rA, ks * 2 + cA);
          lsm4(Ah, sb + ACT_HI + ao);
          lsm4(Al, sb + ACT_LO + ao);
          uint32_t bo = swz(wnA + rB16, ks * 2 + cSel);
          lsm4(Bh, sb + WA_HI + bo);
          lsm4(Bl, sb + WA_LO + bo);
          uint32_t bo2 = swz(wnA + 16 + rB8, ks * 2 + cSel);
          lsm2(Bh2, sb + WA_HI + bo2);
          lsm2(Bl2, sb + WA_LO + bo2);
          mma_bf16(acc0, Ah, Bh);     mma_bf16(acc0, Ah, Bl);     mma_bf16(acc0, Al, Bh);
          mma_bf16(acc1, Ah, Bh + 2); mma_bf16(acc1, Ah, Bl + 2); mma_bf16(acc1, Al, Bh + 2);
          mma_bf16(acc2, Ah, Bh2);    mma_bf16(acc2, Ah, Bl2);    mma_bf16(acc2, Al, Bh2);
        }
      }
      // K-halves reduction via scratch
      if (w >= 4) {
        int base = (w - 4) * 416 + lid * 13;
        #pragma unroll
        for (int e = 0; e < 4; e++) scr[base + e] = acc0[e];
        #pragma unroll
        for (int e = 0; e < 4; e++) scr[base + 4 + e] = acc1[e];
        #pragma unroll
        for (int e = 0; e < 4; e++) scr[base + 8 + e] = acc2[e];
      }
      __syncthreads();
      if (w < 4) {
        int base = w * 416 + lid * 13;
        #pragma unroll
        for (int e = 0; e < 4; e++) acc0[e] += scr[base + e];
        #pragma unroll
        for (int e = 0; e < 4; e++) acc1[e] += scr[base + 4 + e];
        #pragma unroll
        for (int e = 0; e < 4; e++) acc2[e] += scr[base + 8 + e];
        // epilogue: 3 n8-tiles
        #pragma unroll
        for (int j = 0; j < 3; j++) {
          float* a = (j == 0) ? acc0 : (j == 1) ? acc1 : acc2;
          int n = n0A + wnA + j * 8 + tig * 2;
          float2 cc = *(const float2*)&g_ccat[n];
          float v00 = a[0] + cc.x, v01 = a[1] + cc.y;
          float v10 = a[2] + cc.x, v11 = a[3] + cc.y;
          if (n < 512) {            // r gates -> rh split
            int u = n;
            float2 hA = phA[j][0];
            float2 hB = phA[j][1];
            float rh00 = sigmoidf_(v00) * hA.x, rh01 = sigmoidf_(v01) * hA.y;
            float rh10 = sigmoidf_(v10) * hB.x, rh11 = sigmoidf_(v11) * hB.y;
            __nv_bfloat162 ph, pl;
            ph.x = __float2bfloat16(rh00); ph.y = __float2bfloat16(rh01);
            pl.x = __float2bfloat16(rh00 - __bfloat162float(ph.x));
            pl.y = __float2bfloat16(rh01 - __bfloat162float(ph.y));
            *(__nv_bfloat162*)&g_rhh[m1 * 512 + u] = ph;
            *(__nv_bfloat162*)&g_rhl[m1 * 512 + u] = pl;
            ph.x = __float2bfloat16(rh10); ph.y = __float2bfloat16(rh11);
            pl.x = __float2bfloat16(rh10 - __bfloat162float(ph.x));
            pl.y = __float2bfloat16(rh11 - __bfloat162float(ph.y));
            *(__nv_bfloat162*)&g_rhh[m2 * 512 + u] = ph;
            *(__nv_bfloat162*)&g_rhl[m2 * 512 + u] = pl;
          } else if (n < 1024) {    // z preacts
            int u = n - 512;
            *(float2*)&g_Gz[m1 * 512 + u] = make_float2(v00, v01);
            *(float2*)&g_Gz[m2 * 512 + u] = make_float2(v10, v11);
          } else {                  // h preacts
            int u = n - 1024;
            *(float2*)&g_Gh[m1 * 512 + u] = make_float2(v00, v01);
            *(float2*)&g_Gh[m2 * 512 + u] = make_float2(v10, v11);
          }
        }
      }
    }
    gbar();

    // ================= Stage B =================
    {
      // prefetch epilogue operands (warps 0-3)
      float2 pgz[2], pgh[2], phh[2];
      const int nB = n0B + wnB + tig * 2;
      if (w < 4) {
        #pragma unroll
        for (int rr = 0; rr < 2; rr++) {
          int m = m1 + rr * 8;
          pgz[rr] = __ldcg((const float2*)&g_Gz[m * 512 + nB]);
          pgh[rr] = __ldcg((const float2*)&g_Gh[m * 512 + nB]);
          phh[rr] = __ldcg((const float2*)&g_h[m * 512 + nB]);
        }
      }
      #pragma unroll
      for (int kc2 = 0; kc2 < 2; kc2++) {
        int kc = half * 2 + kc2;
        #pragma unroll
        for (int i = 0; i < 4; i++) {
          int idx = ltid + i * 128, r = idx >> 4, cs = idx & 15;
          int go = (m0 + r) * 512 + kc * 128 + cs * 8;
          cp16(sb + ACT_HI + swz(r, kc * 16 + cs), &g_rhh[go]);
          cp16(sb + ACT_LO + swz(r, kc * 16 + cs), &g_rhl[go]);
        }
        CP_COMMIT();
      }
      float acc[4] = {};
      #pragma unroll
      for (int kc2 = 0; kc2 < 2; kc2++) {
        if (kc2 == 0) CP_WAIT(1); else CP_WAIT(0);
        NB_SYNC(1 + wk);
        #pragma unroll
        for (int s = 0; s < 8; s++) {
          int ks = (wk * 2 + kc2) * 8 + s;
          uint32_t Ah[4], Al[4], Bh2[2], Bl2[2];
          uint32_t ao = swz(rA, ks * 2 + cA);
          lsm4(Ah, sb + ACT_HI + ao);
          lsm4(Al, sb + ACT_LO + ao);
          uint32_t bo = swz(wnB + rB8, ks * 2 + cSel);
          lsm2(Bh2, sb + WB_HI + bo);
          lsm2(Bl2, sb + WB_LO + bo);
          mma_bf16(acc, Ah, Bh2);
          mma_bf16(acc, Ah, Bl2);
          mma_bf16(acc, Al, Bh2);
        }
      }
      if (w >= 4) {
        int base = (w - 4) * 160 + lid * 5;
        #pragma unroll
        for (int e = 0; e < 4; e++) scr[base + e] = acc[e];
      }
      __syncthreads();
      if (w < 4) {
        int base = w * 160 + lid * 5;
        #pragma unroll
        for (int e = 0; e < 4; e++) acc[e] += scr[base + e];
        // gating epilogue
        #pragma unroll
        for (int rr = 0; rr < 2; rr++) {
          int m = m1 + rr * 8;
          float q0 = acc[rr * 2 + 0], q1 = acc[rr * 2 + 1];
          float z0 = sigmoidf_(pgz[rr].x), z1 = sigmoidf_(pgz[rr].y);
          float hp0 = tanhf(pgh[rr].x + q0), hp1 = tanhf(pgh[rr].y + q1);
          float hn0 = fminf(fmaxf(fmaf(z0, hp0 - phh[rr].x, phh[rr].x), -5.f), 5.f);
          float hn1 = fminf(fmaxf(fmaf(z1, hp1 - phh[rr].y, phh[rr].y), -5.f), 5.f);
          *(float2*)&g_h[m * 512 + nB] = make_float2(hn0, hn1);
          __nv_bfloat162 ph, pl;
          ph.x = __float2bfloat16(hn0); ph.y = __float2bfloat16(hn1);
          pl.x = __float2bfloat16(hn0 - __bfloat162float(ph.x));
          pl.y = __float2bfloat16(hn1 - __bfloat162float(ph.y));
          *(__nv_bfloat162*)&g_hh[m * 512 + nB] = ph;
          *(__nv_bfloat162*)&g_hl[m * 512 + nB] = pl;
          size_t ho = (size_t)(t - 1) * (B_ * H_) + m * 512 + nB;
          *(__nv_bfloat162*)&g_histh[ho] = ph;
          *(__nv_bfloat162*)&g_histl[ho] = pl;
        }
      }
    }
    gbar();
  }
}

// ---------------- final projection: out[:,1..,:] = hist @ Wo + bo (bf16x3 MMA) ----------------
__global__ void __launch_bounds__(256)
proj_kernel(float* __restrict__ out, const float* __restrict__ bo) {
  extern __shared__ char dsm[];
  const uint32_t sb = smem_u32(dsm);
  const int tid = threadIdx.x, w = tid >> 5, lid = tid & 31;
  const int g = lid >> 2, tig = lid & 3;
  const int by = blockIdx.y;
  const int n0 = blockIdx.x * 128;
  const int wm = (w & 3) * 32;
  const int wn = (w >> 2) * 64;
  const size_t mbase = (size_t)by * 128;
  float acc[2][8][4] = {};

  #pragma unroll 1
  for (int kc = 0; kc < 8; kc++) {
    if (kc == 0) {
      #pragma unroll
      for (int i = 0; i < 4; i++) {
        int idx = tid + i * 256, r = idx >> 3, c = idx & 7;
        uint32_t sw = swz128(r, c);
        size_t eA = (mbase + r) * 512 + c * 8;
        int eB = (n0 + r) * 512 + c * 8;
        cp16(sb + sw, &g_histh[eA]);
        cp16(sb + 16384 + sw, &g_histl[eA]);
        cp16(sb + 32768 + sw, &g_Woth[eB]);
        cp16(sb + 49152 + sw, &g_Wotl[eB]);
      }
      CP_COMMIT();
    }
    if (kc < 7) {
      uint32_t base = sb + ((kc + 1) & 1) * 65536;
      int ko = (kc + 1) * 64;
      #pragma unroll
      for (int i = 0; i < 4; i++) {
        int idx = tid + i * 256, r = idx >> 3, c = idx & 7;
        uint32_t sw = swz128(r, c);
        size_t eA = (mbase + r) * 512 + ko + c * 8;
        int eB = (n0 + r) * 512 + ko + c * 8;
        cp16(base + sw, &g_histh[eA]);
        cp16(base + 16384 + sw, &g_histl[eA]);
        cp16(base + 32768 + sw, &g_Woth[eB]);
        cp16(base + 49152 + sw, &g_Wotl[eB]);
      }
      CP_COMMIT();
      CP_WAIT(1);
    } else {
      CP_WAIT(0);
    }
    __syncthreads();
    uint32_t base = sb + (kc & 1) * 65536;
    #pragma unroll
    for (int s = 0; s < 4; s++) {
      int cA = 2 * s + (lid >> 4);
      int cB = 2 * s + ((lid >> 3) & 1);
      uint32_t Ah[2][4], Al[2][4];
      #pragma unroll
      for (int mt = 0; mt < 2; mt++) {
        int rA = wm + mt * 16 + (lid & 15);
        uint32_t aAddr = base + swz128(rA, cA);
        lsm4(Ah[mt], aAddr);
        lsm4(Al[mt], aAddr + 16384);
      }
      #pragma unroll
      for (int p = 0; p < 4; p++) {
        int rB = wn + p * 16 + (lid & 7) + ((lid >> 4) << 3);
        uint32_t bAddr = base + 32768 + swz128(rB, cB);
        uint32_t Bh[4], Bl[4];
        lsm4(Bh, bAddr);
        lsm4(Bl, bAddr + 16384);
        #pragma unroll
        for (int mt = 0; mt < 2; mt++) {
          mma_bf16(acc[mt][2 * p], Ah[mt], Bh);
          mma_bf16(acc[mt][2 * p], Ah[mt], Bl);
          mma_bf16(acc[mt][2 * p], Al[mt], Bh);
          mma_bf16(acc[mt][2 * p + 1], Ah[mt], Bh + 2);
          mma_bf16(acc[mt][2 * p + 1], Ah[mt], Bl + 2);
          mma_bf16(acc[mt][2 * p + 1], Al[mt], Bh + 2);
        }
      }
    }
    __syncthreads();
  }
  #pragma unroll
  for (int mt = 0; mt < 2; mt++) {
    #pragma unroll
    for (int nt = 0; nt < 8; nt++) {
      int n = n0 + wn + nt * 8 + tig * 2;
      float2 bb = *(const float2*)&bo[n];
      #pragma unroll
      for (int rr = 0; rr < 2; rr++) {
        int b = wm + mt * 16 + g + rr * 8;
        float v0 = acc[mt][nt][rr * 2 + 0] + bb.x;
        float v1 = acc[mt][nt][rr * 2 + 1] + bb.y;
        *(float2*)&out[(size_t)b * ((size_t)T_ * D_) + (size_t)(by + 1) * D_ + n] =
            make_float2(v0, v1);
      }
    }
  }
}

// ---------------- setup SIMT GEMM + helpers ----------------
struct EpiFold {
  const float *Ur, *Uz;
  __device__ __forceinline__ void operator()(int m, int n, float v) const {
    if (n < H_)            v += Ur[m * H_ + n];
    else if (n < 2 * H_)   v += Uz[m * H_ + (n - H_)];
    g_Acat[m * NG_ + n] = v;
  }
};
struct EpiStep1 {
  __device__ __forceinline__ void operator()(int m, int n, float v) const {
    v += g_bpack[H_ + n];
    if (n < H_) g_Gz[m * H_ + n] = v;
    else        g_Gh[m * H_ + (n - H_)] = v;
  }
};

template <int BN, class Epi>
__global__ void __launch_bounds__(4 * BN)
gemm_kernel(const float* __restrict__ A, const float* __restrict__ Bm,
            int K, int ldb, Epi epi) {
  constexpr int BM = 32, BK = 32;
  constexpr int NTHR = 4 * BN;
  __shared__ __align__(16) float As[BK][BM + 1];
  __shared__ __align__(16) float Bs[BK][BN];
  const int tid = threadIdx.x;
  const int bm = blockIdx.y * BM;
  const int bn = blockIdx.x * BN;
  const int tx = tid % (BN / 4);
  const int ty = tid / (BN / 4);
  float acc[2][4] = {};
  for (int k0 = 0; k0 < K; k0 += BK) {
    #pragma unroll
    for (int i = tid * 4; i < BM * BK; i += NTHR * 4) {
      int m = i / BK, k = i % BK;
      float4 v = *(const float4*)(A + (size_t)(bm + m) * K + k0 + k);
      As[k + 0][m] = v.x; As[k + 1][m] = v.y; As[k + 2][m] = v.z; As[k + 3][m] = v.w;
    }
    #pragma unroll
    for (int i = tid * 4; i < BK * BN; i += NTHR * 4) {
      int k = i / BN, n = i % BN;
      *(float4*)&Bs[k][n] = *(const float4*)(Bm + (size_t)(k0 + k) * ldb + bn + n);
    }
    __syncthreads();
    #pragma unroll
    for (int kk = 0; kk < BK; kk++) {
      float a0 = As[kk][ty * 2 + 0];
      float a1 = As[kk][ty * 2 + 1];
      float4 b4 = *(float4*)&Bs[kk][tx * 4];
      acc[0][0] = fmaf(a0, b4.x, acc[0][0]);
      acc[0][1] = fmaf(a0, b4.y, acc[0][1]);
      acc[0][2] = fmaf(a0, b4.z, acc[0][2]);
      acc[0][3] = fmaf(a0, b4.w, acc[0][3]);
      acc[1][0] = fmaf(a1, b4.x, acc[1][0]);
      acc[1][1] = fmaf(a1, b4.y, acc[1][1]);
      acc[1][2] = fmaf(a1, b4.z, acc[1][2]);
      acc[1][3] = fmaf(a1, b4.w, acc[1][3]);
    }
    __syncthreads();
  }
  #pragma unroll
  for (int i = 0; i < 2; i++)
    #pragma unroll
    for (int j = 0; j < 4; j++)
      epi(bm + ty * 2 + i, bn + tx * 4 + j, acc[i][j]);
}

__global__ void pack_kernel(const float* __restrict__ Wr, const float* __restrict__ Wz,
                            const float* __restrict__ Wh, const float* __restrict__ br,
                            const float* __restrict__ bz, const float* __restrict__ bh) {
  int idx = blockIdx.x * blockDim.x + threadIdx.x;
  if (idx == 0) g_bar_arrive = 0;
  if (idx < NG_) {
    int sel = idx >> 9, jl = idx & 511;
    g_bpack[idx] = (sel == 0) ? br[jl] : (sel == 1) ? bz[jl] : bh[jl];
  }
  if (idx < D_ * NG_) {
    int d = idx / NG_, j = idx % NG_;
    int sel = j >> 9, jl = j & 511;
    const float* W = (sel == 0) ? Wr : (sel == 1) ? Wz : Wh;
    g_Wpack[idx] = W[d * H_ + jl];
  }
}

__global__ void ccat_kernel(const float* __restrict__ bo) {
  int w = (blockIdx.x * blockDim.x + threadIdx.x) >> 5;
  int lane = threadIdx.x & 31;
  if (w >= NG_) return;
  float acc = 0.f;
  for (int d = lane; d < D_; d += 32)
    acc = fmaf(bo[d], g_Wpack[(size_t)d * NG_ + w], acc);
  #pragma unroll
  for (int o = 16; o; o >>= 1) acc += __shfl_xor_sync(0xffffffffu, acc, o);
  if (lane == 0) g_ccat[w] = acc + g_bpack[w];
}

__global__ void split_kernel(const float* __restrict__ Uh, const float* __restrict__ Wo) {
  int idx = blockIdx.x * blockDim.x + threadIdx.x;
  if (idx < NG_ * H_) {
    int m = idx >> 9, k = idx & 511;
    float x = g_Acat[(size_t)k * NG_ + m];
    __nv_bfloat16 hi = __float2bfloat16(x);
    g_Ath[idx] = hi;
    g_Atl[idx] = __float2bfloat16(x - __bfloat162float(hi));
  }
  if (idx < H_ * H_) {
    int n = idx >> 9, k = idx & 511;
    float x = Uh[(size_t)k * H_ + n];
    __nv_bfloat16 hi = __float2bfloat16(x);
    g_Uth[idx] = hi;
    g_Utl[idx] = __float2bfloat16(x - __bfloat162float(hi));
    float y = Wo[(size_t)k * D_ + n];
    __nv_bfloat16 hi2 = __float2bfloat16(y);
    g_Woth[idx] = hi2;
    g_Wotl[idx] = __float2bfloat16(y - __bfloat162float(hi2));
  }
}

__global__ void copy0_kernel(const float* __restrict__ inputs, float* __restrict__ out) {
  int idx = blockIdx.x * blockDim.x + threadIdx.x;
  if (idx >= B_ * D_) return;
  int b = idx / D_, d = idx % D_;
  out[(size_t)b * ((size_t)T_ * D_) + d] = inputs[idx];
}

__global__ void combine1_kernel() {
  int idx = blockIdx.x * blockDim.x + threadIdx.x;
  if (idx >= B_ * H_) return;
  float z  = sigmoidf_(g_Gz[idx]);
  float hp = tanhf(g_Gh[idx]);
  float hn = fminf(fmaxf(z * hp, -5.f), 5.f);
  g_h[idx] = hn;
  __nv_bfloat16 hi = __float2bfloat16(hn);
  __nv_bfloat16 lo = __float2bfloat16(hn - __bfloat162float(hi));
  g_hh[idx] = hi;
  g_hl[idx] = lo;
  g_histh[idx] = hi;
  g_histl[idx] = lo;
}

// ---------------- launch ----------------
extern "C" void kernel_launch(void* const* d_in, const int* in_sizes, int n_in,
                              void* d_out, int out_size) {
  const float* inputs = (const float*)d_in[0];
  const float* Wz = (const float*)d_in[1];
  const float* Wr = (const float*)d_in[2];
  const float* Wh = (const float*)d_in[3];
  const float* Uz = (const float*)d_in[4];
  const float* Ur = (const float*)d_in[5];
  const float* Uh = (const float*)d_in[6];
  const float* bz = (const float*)d_in[7];
  const float* br = (const float*)d_in[8];
  const float* bh = (const float*)d_in[9];
  const float* Wo = (const float*)d_in[10];
  const float* bo = (const float*)d_in[11];
  float* out = (float*)d_out;

  float* pWpack;
  cudaGetSymbolAddress((void**)&pWpack, g_Wpack);

  cudaFuncSetAttribute(proj_kernel, cudaFuncAttributeMaxDynamicSharedMemorySize, 131072);
  cudaFuncSetAttribute(recur_kernel, cudaFuncAttributeMaxDynamicSharedMemorySize, RSMEM);

  // setup: pack + fold + bf16 splits
  pack_kernel<<<(D_ * NG_ + 255) / 256, 256>>>(Wr, Wz, Wh, br, bz, bh);
  ccat_kernel<<<(NG_ * 32 + 255) / 256, 256>>>(bo);
  gemm_kernel<64, EpiFold><<<dim3(NG_ / 64, H_ / 32), 256>>>(
      Wo, pWpack, D_, NG_, EpiFold{Ur, Uz});
  split_kernel<<<(NG_ * H_ + 255) / 256, 256>>>(Uh, Wo);

  // step 1 (h0 = 0)
  gemm_kernel<64, EpiStep1><<<dim3(1024 / 64, B_ / 32), 256>>>(
      inputs, pWpack + H_, D_, NG_, EpiStep1{});
  combine1_kernel<<<(B_ * H_ + 255) / 256, 256>>>();

  // steps 2..T-1: persistent bf16x3 mma kernel, K-split across warp halves
  recur_kernel<<<NCTA, 256, RSMEM>>>();

  // t = 0 output is the raw input
  copy0_kernel<<<(B_ * D_ + 255) / 256, 256>>>(inputs, out);

  // deferred output projection (bf16x3 mma)
  proj_kernel<<<dim3(4, T_ - 1), 256, 131072>>>(out, bo);
}